// round 12
// baseline (speedup 1.0000x reference)
#include <cuda_runtime.h>
#include <cuda_bf16.h>
#include <cuda_fp16.h>
#include <math.h>
#include <stdint.h>

// ---------------- problem constants ----------------
#define NMAX 100000
#define EMAX 1200000

// ---------------- device scratch ----------------
__device__ float d_XC[(size_t)NMAX * 64];        // h1 (fp32, for head)
__device__ __half d_XCh[(size_t)NMAX * 64];      // h1 (fp16, for gather1)
__device__ float d_agg[(size_t)NMAX * 128];      // gather output
__device__ float d_ybuf[(size_t)NMAX * 64];      // pre-BN output (reused)
__device__ float d_Tdeg[65 * 128];
__device__ float d_Tlab[16 * 128];
__device__ float d_Fdeg[65 * 64];
__device__ float d_Flab[16 * 64];
__device__ int   d_code[NMAX];
__device__ int   d_cnt[NMAX];
__device__ int   d_cursor[NMAX];
__device__ int   d_rowstart[NMAX + 1];
__device__ int   d_col[EMAX];
__device__ int   d_bsum[128];
__device__ float d_sum[3 * 64];
__device__ float d_sq[3 * 64];

__device__ __forceinline__ float lrelu(float x) { return x > 0.f ? x : 0.01f * x; }

__device__ __forceinline__ float to_tf32(float x) {
    float r;
    asm("cvt.rna.tf32.f32 %0, %1;" : "=f"(r) : "f"(x));
    return r;
}

// mma.sync m16n8k8 tf32: D += A(16x8) * B(8x8), fp32 accumulate
__device__ __forceinline__ void mma_tf32(float (&d)[4], const uint32_t (&a)[4], const uint32_t (&b)[2]) {
    asm volatile("mma.sync.aligned.m16n8k8.row.col.f32.tf32.tf32.f32 "
        "{%0,%1,%2,%3}, {%4,%5,%6,%7}, {%8,%9}, {%0,%1,%2,%3};"
        : "+f"(d[0]), "+f"(d[1]), "+f"(d[2]), "+f"(d[3])
        : "r"(a[0]), "r"(a[1]), "r"(a[2]), "r"(a[3]), "r"(b[0]), "r"(b[1]));
}

// ---------------- init (zero + code pack) and dictionary tables, merged ----------------
__global__ void zero_tables_kernel(const int* __restrict__ deg, const int* __restrict__ lab,
                                   const float* __restrict__ emb_deg,
                                   const float* __restrict__ emb_lab,
                                   const float* __restrict__ l0_w1,
                                   const float* __restrict__ fc_w1,
                                   int n, int nz) {
    __shared__ float e[64];
    int t = threadIdx.x;
    if ((int)blockIdx.x < nz) {
        int i = blockIdx.x * 256 + t;
        if (i < n) {
            d_cnt[i] = 0;
            d_code[i] = (deg[i] << 4) | lab[i];
        }
        if (i < 192) { d_sum[i] = 0.f; d_sq[i] = 0.f; }
        return;
    }
    int b = blockIdx.x - nz;
    const float* erow; const float* w; float* out; int H;
    if (b < 65)       { erow = emb_deg + b * 64;         w = l0_w1;            out = d_Tdeg + b * 128;         H = 128; }
    else if (b < 81)  { erow = emb_lab + (b - 65) * 64;  w = l0_w1 + 64 * 128; out = d_Tlab + (b - 65) * 128;  H = 128; }
    else if (b < 146) { erow = emb_deg + (b - 81) * 64;  w = fc_w1;            out = d_Fdeg + (b - 81) * 64;   H = 64;  }
    else              { erow = emb_lab + (b - 146) * 64; w = fc_w1 + 64 * 64;  out = d_Flab + (b - 146) * 64;  H = 64;  }
    if (t < 64) e[t] = erow[t];
    __syncthreads();
    if (t < H) {
        float s = 0.f;
        #pragma unroll 8
        for (int k = 0; k < 64; k++) s += e[k] * w[k * H + t];
        out[t] = s;
    }
}

// ---------------- CSR build ----------------
__global__ void count_kernel(const int* __restrict__ edge, int e) {
    int i = blockIdx.x * blockDim.x + threadIdx.x;
    if (i < e) atomicAdd(&d_cnt[edge[e + i]], 1);
}

__global__ void scanA_kernel(int n) {
    __shared__ int wsum[32];
    int t = threadIdx.x;
    int idx = blockIdx.x * 1024 + t;
    int v = (idx < n) ? d_cnt[idx] : 0;
    #pragma unroll
    for (int o = 16; o; o >>= 1) v += __shfl_xor_sync(0xffffffffu, v, o);
    if ((t & 31) == 0) wsum[t >> 5] = v;
    __syncthreads();
    if (t < 32) {
        int s = wsum[t];
        #pragma unroll
        for (int o = 16; o; o >>= 1) s += __shfl_xor_sync(0xffffffffu, s, o);
        if (t == 0) d_bsum[blockIdx.x] = s;
    }
}

// scanC with integrated block-offset scan; also initializes cursor = rowstart
__global__ void scanC_kernel(int n, int nb) {
    __shared__ int wsum[32];
    __shared__ int sb[128];
    int t = threadIdx.x;
    if (t < 128) sb[t] = (t < nb) ? d_bsum[t] : 0;
    __syncthreads();
    #pragma unroll
    for (int o = 1; o < 128; o <<= 1) {
        int u = (t < 128 && t >= o) ? sb[t - o] : 0;
        __syncthreads();
        if (t < 128) sb[t] += u;
        __syncthreads();
    }
    int boff = (blockIdx.x == 0) ? 0 : sb[blockIdx.x - 1];
    if (blockIdx.x == 0 && t == 0) d_rowstart[n] = sb[nb - 1];

    int idx = blockIdx.x * 1024 + t;
    int v = (idx < n) ? d_cnt[idx] : 0;
    int lane = t & 31, wid = t >> 5;
    int inc = v;
    #pragma unroll
    for (int o = 1; o < 32; o <<= 1) {
        int u = __shfl_up_sync(0xffffffffu, inc, o);
        if (lane >= o) inc += u;
    }
    if (lane == 31) wsum[wid] = inc;
    __syncthreads();
    if (t < 32) {
        int s = wsum[t];
        int sInc = s;
        #pragma unroll
        for (int o = 1; o < 32; o <<= 1) {
            int u = __shfl_up_sync(0xffffffffu, sInc, o);
            if (t >= o) sInc += u;
        }
        wsum[t] = sInc - s;
    }
    __syncthreads();
    if (idx < n) {
        int rs = boff + wsum[wid] + inc - v;
        d_rowstart[idx] = rs;
        d_cursor[idx] = rs;
    }
}

__global__ void fill_kernel(const int* __restrict__ edge, int e) {
    int i = blockIdx.x * blockDim.x + threadIdx.x;
    if (i < e) {
        int d = edge[e + i];
        int p = atomicAdd(&d_cursor[d], 1);
        d_col[p] = edge[i];
    }
}

// ---------------- layer-0 aggregation from fp16 smem dictionary tables ----------------
__global__ void __launch_bounds__(256)
gather0_kernel(const float* __restrict__ epsp, const float* __restrict__ b1, int n) {
    __shared__ __align__(8) __half sTd[65 * 128];
    __shared__ __align__(8) __half sTl[16 * 128];
    int t = threadIdx.x;
    {
        // convert fp32 global tables -> fp16 smem
        const float2* src = (const float2*)d_Tdeg;
        __half2* dst = (__half2*)sTd;
        for (int j = t; j < 65 * 64; j += 256) {
            float2 v = src[j];
            dst[j] = __floats2half2_rn(v.x, v.y);
        }
        const float2* src2 = (const float2*)d_Tlab;
        __half2* dst2 = (__half2*)sTl;
        for (int j = t; j < 16 * 64; j += 256) {
            float2 v = src2[j];
            dst2[j] = __floats2half2_rn(v.x, v.y);
        }
    }
    __syncthreads();
    const uint2* Td2 = (const uint2*)sTd;   // row = 32 uint2 (4 halves each)
    const uint2* Tl2 = (const uint2*)sTl;
    int lane = t & 31, w = t >> 5;
    int c = lane;
    float e1 = 1.0f + epsp[0];
    float4 b4 = ((const float4*)b1)[c];
    int base_node = blockIdx.x * 256 + w * 32;
    for (int it = 0; it < 32; it++) {
        int i = base_node + it;
        if (i >= n) break;
        int js = d_rowstart[i], je = d_rowstart[i + 1];
        int self = d_code[i];
        uint2 ua = Td2[(self >> 4) * 32 + c];
        uint2 ub = Tl2[(self & 15) * 32 + c];
        float2 a01 = __half22float2(*(const __half2*)&ua.x);
        float2 a23 = __half22float2(*(const __half2*)&ua.y);
        float2 l01 = __half22float2(*(const __half2*)&ub.x);
        float2 l23 = __half22float2(*(const __half2*)&ub.y);
        float4 s = make_float4(e1 * (a01.x + l01.x), e1 * (a01.y + l01.y),
                               e1 * (a23.x + l23.x), e1 * (a23.y + l23.y));
        for (int bs = js; bs < je; bs += 32) {
            int idx = bs + lane;
            int code = (idx < je) ? d_code[d_col[idx]] : 0;
            int m = min(32, je - bs);
            for (int j = 0; j < m; j++) {
                int cd = __shfl_sync(0xffffffffu, code, j);
                uint2 u = Td2[(cd >> 4) * 32 + c];
                uint2 v = Tl2[(cd & 15) * 32 + c];
                float2 u01 = __half22float2(*(const __half2*)&u.x);
                float2 u23 = __half22float2(*(const __half2*)&u.y);
                float2 v01 = __half22float2(*(const __half2*)&v.x);
                float2 v23 = __half22float2(*(const __half2*)&v.y);
                s.x += u01.x + v01.x; s.y += u01.y + v01.y;
                s.z += u23.x + v23.x; s.w += u23.y + v23.y;
            }
        }
        s.x = lrelu(s.x + b4.x); s.y = lrelu(s.y + b4.y);
        s.z = lrelu(s.z + b4.z); s.w = lrelu(s.w + b4.w);
        ((float4*)d_agg)[(size_t)i * 32 + c] = s;
    }
}

// ---------------- layer-1 aggregation (fp16 source, fp32 accumulate) ----------------
__global__ void gather1_kernel(const float* __restrict__ epsp, int n) {
    int lane = threadIdx.x & 31;
    int warp = (blockIdx.x * blockDim.x + threadIdx.x) >> 5;
    int i = warp * 2 + (lane >> 4);
    int c = lane & 15;
    if (i >= n) return;
    float e1 = 1.0f + epsp[0];
    const uint2* hb2 = (const uint2*)d_XCh;   // row = 16 uint2 (4 halves each)
    uint2 raw = hb2[(size_t)i * 16 + c];
    float2 a01 = __half22float2(*(const __half2*)&raw.x);
    float2 a23 = __half22float2(*(const __half2*)&raw.y);
    float4 s = make_float4(a01.x * e1, a01.y * e1, a23.x * e1, a23.y * e1);
    int js = d_rowstart[i], je = d_rowstart[i + 1];
    for (int j = js; j < je; j++) {
        int nb = d_col[j];
        uint2 r = hb2[(size_t)nb * 16 + c];
        float2 v01 = __half22float2(*(const __half2*)&r.x);
        float2 v23 = __half22float2(*(const __half2*)&r.y);
        s.x += v01.x; s.y += v01.y; s.z += v23.x; s.w += v23.y;
    }
    ((float4*)d_agg)[(size_t)i * 16 + c] = s;
}

// ================= warp-level tf32 MMA GEMM building blocks =================
template <int K>
__device__ __forceinline__ void loadA_mma(float* xs, const float* __restrict__ x,
                                          int node0, int n, int t) {
    constexpr int KP = K + 4;
    int r = t >> 1;
    int cb = (t & 1) * (K / 2);
    int gn = node0 + r;
    const float4* src = (const float4*)(x + (size_t)gn * K + cb);
    #pragma unroll
    for (int i = 0; i < K / 8; i++) {
        float4 v = (gn < n) ? src[i] : make_float4(0.f, 0.f, 0.f, 0.f);
        float* dst = xs + r * KP + cb + i * 4;
        dst[0] = to_tf32(v.x); dst[1] = to_tf32(v.y);
        dst[2] = to_tf32(v.z); dst[3] = to_tf32(v.w);
    }
}

template <int K>
__device__ __forceinline__ void loadB_mma(float* wsT, const float* __restrict__ w, int t) {
    constexpr int KP = K + 4;
    #pragma unroll
    for (int i = 0; i < K * 64 / 256; i++) {
        int idx = t + i * 256;
        int k = idx >> 6, nn = idx & 63;
        wsT[nn * KP + k] = to_tf32(w[idx]);
    }
}

template <int K>
__device__ __forceinline__ void warp_mma(float (&acc)[8][4], const float* xs, const float* wsT,
                                         int rbase, int g, int tig) {
    constexpr int KP = K + 4;
    const float* xr0 = xs + (rbase + g) * KP;
    const float* xr1 = xs + (rbase + g + 8) * KP;
    #pragma unroll
    for (int ks = 0; ks < K / 8; ks++) {
        int k0 = ks * 8;
        uint32_t a[4];
        a[0] = __float_as_uint(xr0[k0 + tig]);
        a[1] = __float_as_uint(xr1[k0 + tig]);
        a[2] = __float_as_uint(xr0[k0 + tig + 4]);
        a[3] = __float_as_uint(xr1[k0 + tig + 4]);
        #pragma unroll
        for (int nt = 0; nt < 8; nt++) {
            const float* wr = wsT + (nt * 8 + g) * KP;
            uint32_t b[2];
            b[0] = __float_as_uint(wr[k0 + tig]);
            b[1] = __float_as_uint(wr[k0 + 4 + tig]);
            mma_tf32(acc[nt], a, b);
        }
    }
}

// stats + store epilogue
__device__ __forceinline__ void mma_store_stats(float (&acc)[8][4],
                                                const float2 (&bb0)[8], const float2 (&bb1)[8],
                                                int r0, int r1, bool v0, bool v1, int tig, int lane,
                                                float* __restrict__ y, float* csum, float* csq) {
    float ps[8][2], pq[8][2];
    #pragma unroll
    for (int nt = 0; nt < 8; nt++) {
        int c = nt * 8 + 2 * tig;
        float v00 = acc[nt][0] + bb0[nt].x, v01 = acc[nt][1] + bb0[nt].y;
        float v10 = acc[nt][2] + bb1[nt].x, v11 = acc[nt][3] + bb1[nt].y;
        float s0 = 0.f, s1 = 0.f, q0 = 0.f, q1 = 0.f;
        if (v0) { s0 += v00; s1 += v01; q0 += v00 * v00; q1 += v01 * v01; }
        if (v1) { s0 += v10; s1 += v11; q0 += v10 * v10; q1 += v11 * v11; }
        ps[nt][0] = s0; ps[nt][1] = s1; pq[nt][0] = q0; pq[nt][1] = q1;
        if (v0) *(float2*)(y + (size_t)r0 * 64 + c) = make_float2(v00, v01);
        if (v1) *(float2*)(y + (size_t)r1 * 64 + c) = make_float2(v10, v11);
    }
    #pragma unroll
    for (int o = 4; o <= 16; o <<= 1) {
        #pragma unroll
        for (int nt = 0; nt < 8; nt++) {
            ps[nt][0] += __shfl_xor_sync(0xffffffffu, ps[nt][0], o);
            ps[nt][1] += __shfl_xor_sync(0xffffffffu, ps[nt][1], o);
            pq[nt][0] += __shfl_xor_sync(0xffffffffu, pq[nt][0], o);
            pq[nt][1] += __shfl_xor_sync(0xffffffffu, pq[nt][1], o);
        }
    }
    if (lane < 4) {
        #pragma unroll
        for (int nt = 0; nt < 8; nt++) {
            int c = nt * 8 + 2 * tig;
            atomicAdd(&csum[c], ps[nt][0]);
            atomicAdd(&csum[c + 1], ps[nt][1]);
            atomicAdd(&csq[c], pq[nt][0]);
            atomicAdd(&csq[c + 1], pq[nt][1]);
        }
    }
}

// ---------------- layer-0 GEMM: y = agg[tile,128] @ w[128,64] + b ----------------
__global__ void __launch_bounds__(256, 2)
mmagemm0_kernel(const float* __restrict__ x, const float* __restrict__ w,
                const float* __restrict__ bias, float* __restrict__ y,
                float* __restrict__ gsum, float* __restrict__ gsq, int n) {
    constexpr int K = 128, KP = K + 4;
    extern __shared__ float sm[];
    float* xs  = sm;
    float* wsT = sm + 128 * KP;
    __shared__ float csum[64], csq[64];

    const int t = threadIdx.x;
    const int lane = t & 31, warp = t >> 5;
    const int g = lane >> 2, tig = lane & 3;
    const int rbase = warp * 16;
    const int node0 = blockIdx.x * 128;

    if (t < 64) { csum[t] = 0.f; csq[t] = 0.f; }
    loadA_mma<K>(xs, x, node0, n, t);
    loadB_mma<K>(wsT, w, t);
    __syncthreads();

    float acc[8][4];
    #pragma unroll
    for (int nt = 0; nt < 8; nt++)
        #pragma unroll
        for (int j = 0; j < 4; j++) acc[nt][j] = 0.f;
    warp_mma<K>(acc, xs, wsT, rbase, g, tig);

    int r0 = node0 + rbase + g, r1 = r0 + 8;
    bool v0 = r0 < n, v1 = r1 < n;
    float2 bb0[8], bb1[8];
    #pragma unroll
    for (int nt = 0; nt < 8; nt++) {
        float2 b2v = *(const float2*)(bias + nt * 8 + 2 * tig);
        bb0[nt] = b2v; bb1[nt] = b2v;
    }
    mma_store_stats(acc, bb0, bb1, r0, r1, v0, v1, tig, lane, y, csum, csq);

    __syncthreads();
    if (t < 64) {
        atomicAdd(&gsum[t], csum[t]);
        atomicAdd(&gsq[t], csq[t]);
    }
}

// ---------------- layer-1 MLP (tf32 MMA): y = lrelu(x@w1+b1)@w2+b2, stats ----------------
__global__ void __launch_bounds__(256, 2)
mmamlp1_kernel(const float* __restrict__ x,
               const float* __restrict__ w1, const float* __restrict__ b1,
               const float* __restrict__ w2, const float* __restrict__ b2,
               float* __restrict__ y,
               float* __restrict__ gsum, float* __restrict__ gsq, int n) {
    constexpr int K = 64, KP = K + 4;
    extern __shared__ float sm[];
    float* xs   = sm;                  // 128 * KP (reused for hidden)
    float* ws1T = sm + 128 * KP;
    float* ws2T = ws1T + 64 * KP;
    __shared__ float csum[64], csq[64];

    const int t = threadIdx.x;
    const int lane = t & 31, warp = t >> 5;
    const int g = lane >> 2, tig = lane & 3;
    const int rbase = warp * 16;
    const int node0 = blockIdx.x * 128;

    if (t < 64) { csum[t] = 0.f; csq[t] = 0.f; }
    loadA_mma<K>(xs, x, node0, n, t);
    loadB_mma<K>(ws1T, w1, t);
    loadB_mma<K>(ws2T, w2, t);
    __syncthreads();

    float acc[8][4];
    #pragma unroll
    for (int nt = 0; nt < 8; nt++)
        #pragma unroll
        for (int j = 0; j < 4; j++) acc[nt][j] = 0.f;

    // stage 1: hidden = lrelu(x @ w1 + b1) -> own xs rows
    warp_mma<K>(acc, xs, ws1T, rbase, g, tig);
    __syncwarp();
    {
        float* xr0 = xs + (rbase + g) * KP;
        float* xr1 = xs + (rbase + g + 8) * KP;
        #pragma unroll
        for (int nt = 0; nt < 8; nt++) {
            int c = nt * 8 + 2 * tig;
            float2 bb = *(const float2*)(b1 + c);
            xr0[c]     = to_tf32(lrelu(acc[nt][0] + bb.x));
            xr0[c + 1] = to_tf32(lrelu(acc[nt][1] + bb.y));
            xr1[c]     = to_tf32(lrelu(acc[nt][2] + bb.x));
            xr1[c + 1] = to_tf32(lrelu(acc[nt][3] + bb.y));
        }
    }
    __syncwarp();

    #pragma unroll
    for (int nt = 0; nt < 8; nt++)
        #pragma unroll
        for (int j = 0; j < 4; j++) acc[nt][j] = 0.f;

    // stage 2: y = hidden @ w2 + b2
    warp_mma<K>(acc, xs, ws2T, rbase, g, tig);

    int r0 = node0 + rbase + g, r1 = r0 + 8;
    bool v0 = r0 < n, v1 = r1 < n;
    float2 bb0[8], bb1[8];
    #pragma unroll
    for (int nt = 0; nt < 8; nt++) {
        float2 b2v = *(const float2*)(b2 + nt * 8 + 2 * tig);
        bb0[nt] = b2v; bb1[nt] = b2v;
    }
    mma_store_stats(acc, bb0, bb1, r0, r1, v0, v1, tig, lane, y, csum, csq);

    __syncthreads();
    if (t < 64) {
        atomicAdd(&gsum[t], csum[t]);
        atomicAdd(&gsq[t], csq[t]);
    }
}

// ---------------- head GEMM: fused BN1-apply on A-load + code rowbias epilogue ----------------
__global__ void __launch_bounds__(256, 2)
headgemm_kernel(const float* __restrict__ XC, const float* __restrict__ ybuf_in,
                const float* __restrict__ w,
                const float* __restrict__ gsum1, const float* __restrict__ gsq1,
                const float* __restrict__ bn1g, const float* __restrict__ bn1b,
                const float* __restrict__ fc_b1,
                float* __restrict__ y,
                float* __restrict__ gsum, float* __restrict__ gsq, int n) {
    constexpr int K = 128, KP = K + 4;
    extern __shared__ float sm[];
    float* xs  = sm;
    float* wsT = sm + 128 * KP;
    __shared__ float csum[64], csq[64], sc[64], sh[64];

    const int t = threadIdx.x;
    const int lane = t & 31, warp = t >> 5;
    const int g = lane >> 2, tig = lane & 3;
    const int rbase = warp * 16;
    const int node0 = blockIdx.x * 128;

    if (t < 64) {
        csum[t] = 0.f; csq[t] = 0.f;
        float invn = 1.0f / (float)n;
        float m = gsum1[t] * invn;
        float var = gsq1[t] * invn - m * m;
        float s = bn1g[t] * rsqrtf(var + 1e-5f);
        sc[t] = s; sh[t] = bn1b[t] - m * s;
    }
    __syncthreads();

    loadB_mma<K>(wsT, w, t);
    // A tile: cols 0..63 = h1 (XC), cols 64..127 = h2 = lrelu(bn1(ybuf))
    {
        int r = t >> 1;
        int gn = node0 + r;
        if ((t & 1) == 0) {
            const float4* src = (const float4*)(XC + (size_t)gn * 64);
            float* dst = xs + r * KP;
            #pragma unroll
            for (int i = 0; i < 16; i++) {
                float4 v = (gn < n) ? src[i] : make_float4(0.f, 0.f, 0.f, 0.f);
                dst[i * 4 + 0] = to_tf32(v.x); dst[i * 4 + 1] = to_tf32(v.y);
                dst[i * 4 + 2] = to_tf32(v.z); dst[i * 4 + 3] = to_tf32(v.w);
            }
        } else {
            const float4* src = (const float4*)(ybuf_in + (size_t)gn * 64);
            float* dst = xs + r * KP + 64;
            #pragma unroll
            for (int i = 0; i < 16; i++) {
                float4 v = (gn < n) ? src[i] : make_float4(0.f, 0.f, 0.f, 0.f);
                int c = i * 4;
                dst[c + 0] = to_tf32(lrelu(v.x * sc[c + 0] + sh[c + 0]));
                dst[c + 1] = to_tf32(lrelu(v.y * sc[c + 1] + sh[c + 1]));
                dst[c + 2] = to_tf32(lrelu(v.z * sc[c + 2] + sh[c + 2]));
                dst[c + 3] = to_tf32(lrelu(v.w * sc[c + 3] + sh[c + 3]));
            }
        }
    }
    __syncthreads();

    float acc[8][4];
    #pragma unroll
    for (int nt = 0; nt < 8; nt++)
        #pragma unroll
        for (int j = 0; j < 4; j++) acc[nt][j] = 0.f;
    warp_mma<K>(acc, xs, wsT, rbase, g, tig);

    int r0 = node0 + rbase + g, r1 = r0 + 8;
    bool v0 = r0 < n, v1 = r1 < n;
    int code0 = v0 ? d_code[r0] : 0;
    int code1 = v1 ? d_code[r1] : 0;
    const float* fd0 = d_Fdeg + (code0 >> 4) * 64;
    const float* fl0 = d_Flab + (code0 & 15) * 64;
    const float* fd1 = d_Fdeg + (code1 >> 4) * 64;
    const float* fl1 = d_Flab + (code1 & 15) * 64;
    float2 bb0[8], bb1[8];
    #pragma unroll
    for (int nt = 0; nt < 8; nt++) {
        int c = nt * 8 + 2 * tig;
        float2 fb = *(const float2*)(fc_b1 + c);
        float2 a0 = *(const float2*)(fd0 + c);
        float2 l0 = *(const float2*)(fl0 + c);
        float2 a1 = *(const float2*)(fd1 + c);
        float2 l1 = *(const float2*)(fl1 + c);
        bb0[nt] = make_float2(a0.x + l0.x + fb.x, a0.y + l0.y + fb.y);
        bb1[nt] = make_float2(a1.x + l1.x + fb.x, a1.y + l1.y + fb.y);
    }
    mma_store_stats(acc, bb0, bb1, r0, r1, v0, v1, tig, lane, y, csum, csq);

    __syncthreads();
    if (t < 64) {
        atomicAdd(&gsum[t], csum[t]);
        atomicAdd(&gsq[t], csq[t]);
    }
}

// ---------------- BN apply + lrelu (layer 0): writes fp32 XC + fp16 XCh ----------------
__global__ void bnapply_kernel(const float* __restrict__ y,
                               const float* __restrict__ gsum, const float* __restrict__ gsq,
                               const float* __restrict__ g, const float* __restrict__ b,
                               float* __restrict__ out, int n) {
    __shared__ float sc[64], sh[64];
    int t = threadIdx.x;
    if (t < 64) {
        float invn = 1.0f / (float)n;
        float m = gsum[t] * invn;
        float var = gsq[t] * invn - m * m;
        float s = g[t] * rsqrtf(var + 1e-5f);
        sc[t] = s; sh[t] = b[t] - m * s;
    }
    __syncthreads();
    int idx = blockIdx.x * blockDim.x + t;
    int i = idx >> 4, c = idx & 15;
    if (i >= n) return;
    float4 v = ((const float4*)y)[(size_t)i * 16 + c];
    v.x = lrelu(v.x * sc[c * 4 + 0] + sh[c * 4 + 0]);
    v.y = lrelu(v.y * sc[c * 4 + 1] + sh[c * 4 + 1]);
    v.z = lrelu(v.z * sc[c * 4 + 2] + sh[c * 4 + 2]);
    v.w = lrelu(v.w * sc[c * 4 + 3] + sh[c * 4 + 3]);
    ((float4*)out)[(size_t)i * 16 + c] = v;
    // fp16 copy for gather1
    uint2 pk;
    __half2 p0 = __floats2half2_rn(v.x, v.y);
    __half2 p1 = __floats2half2_rn(v.z, v.w);
    pk.x = *(const uint32_t*)&p0;
    pk.y = *(const uint32_t*)&p1;
    ((uint2*)d_XCh)[(size_t)i * 16 + c] = pk;
}

// ---------------- head: lrelu(bn(y)) @ fc_w2 + b2 -> sigmoid ----------------
__global__ void head_kernel(const float* __restrict__ y,
                            const float* __restrict__ gsum, const float* __restrict__ gsq,
                            const float* __restrict__ g, const float* __restrict__ b,
                            const float* __restrict__ w2, const float* __restrict__ b2,
                            float* __restrict__ out, int n) {
    __shared__ float sc[64], sh[64];
    int t = threadIdx.x;
    if (t < 64) {
        float invn = 1.0f / (float)n;
        float m = gsum[t] * invn;
        float var = gsq[t] * invn - m * m;
        float s = g[t] * rsqrtf(var + 1e-5f);
        sc[t] = s; sh[t] = b[t] - m * s;
    }
    __syncthreads();
    int lane = t & 31;
    int i = (blockIdx.x * blockDim.x + t) >> 5;
    if (i >= n) return;
    float2 v = ((const float2*)y)[(size_t)i * 32 + lane];
    float z0 = lrelu(v.x * sc[2 * lane] + sh[2 * lane]);
    float z1 = lrelu(v.y * sc[2 * lane + 1] + sh[2 * lane + 1]);
    float a = z0 * w2[2 * lane] + z1 * w2[2 * lane + 1];
    #pragma unroll
    for (int o = 16; o; o >>= 1) a += __shfl_xor_sync(0xffffffffu, a, o);
    if (lane == 0) out[i] = 1.0f / (1.0f + expf(-(a + b2[0])));
}

// ---------------- launch ----------------
extern "C" void kernel_launch(void* const* d_in, const int* in_sizes, int n_in,
                              void* d_out, int out_size) {
    const int*   node_deg = (const int*)d_in[0];
    const int*   node_lab = (const int*)d_in[1];
    const int*   edge     = (const int*)d_in[2];
    const float* emb_deg  = (const float*)d_in[3];
    const float* emb_lab  = (const float*)d_in[4];
    const float* l0_w1 = (const float*)d_in[5];
    const float* l0_b1 = (const float*)d_in[6];
    const float* l0_w2 = (const float*)d_in[7];
    const float* l0_b2 = (const float*)d_in[8];
    const float* l0_eps = (const float*)d_in[9];
    const float* bn0_g = (const float*)d_in[10];
    const float* bn0_b = (const float*)d_in[11];
    const float* l1_w1 = (const float*)d_in[12];
    const float* l1_b1 = (const float*)d_in[13];
    const float* l1_w2 = (const float*)d_in[14];
    const float* l1_b2 = (const float*)d_in[15];
    const float* l1_eps = (const float*)d_in[16];
    const float* bn1_g = (const float*)d_in[17];
    const float* bn1_b = (const float*)d_in[18];
    const float* fc_w1 = (const float*)d_in[19];
    const float* fc_b1 = (const float*)d_in[20];
    const float* fc_bn_g = (const float*)d_in[21];
    const float* fc_bn_b = (const float*)d_in[22];
    const float* fc_w2 = (const float*)d_in[23];
    const float* fc_b2 = (const float*)d_in[24];

    int n = in_sizes[0];
    int E = in_sizes[2] / 2;

    float *XC, *agg, *ybuf, *sumv, *sqv;
    cudaGetSymbolAddress((void**)&XC,   d_XC);
    cudaGetSymbolAddress((void**)&agg,  d_agg);
    cudaGetSymbolAddress((void**)&ybuf, d_ybuf);
    cudaGetSymbolAddress((void**)&sumv, d_sum);
    cudaGetSymbolAddress((void**)&sqv,  d_sq);

    const int SMEM_GEMM128 = (128 + 64) * (128 + 4) * 4;       // 101376
    const int SMEM_MLP     = (128 + 64 + 64) * (64 + 4) * 4;   // 69632
    cudaFuncSetAttribute(mmagemm0_kernel, cudaFuncAttributeMaxDynamicSharedMemorySize, SMEM_GEMM128);
    cudaFuncSetAttribute(headgemm_kernel, cudaFuncAttributeMaxDynamicSharedMemorySize, SMEM_GEMM128);
    cudaFuncSetAttribute(mmamlp1_kernel,  cudaFuncAttributeMaxDynamicSharedMemorySize, SMEM_MLP);

    int NB = (n + 1023) / 1024;
    int NZ = (n + 255) / 256;
    int NT = (n + 127) / 128;

    // init (+tables) + CSR build
    zero_tables_kernel<<<NZ + 162, 256>>>(node_deg, node_lab, emb_deg, emb_lab, l0_w1, fc_w1, n, NZ);
    count_kernel<<<(E + 255) / 256, 256>>>(edge, E);
    scanA_kernel<<<NB, 1024>>>(n);
    scanC_kernel<<<NB, 1024>>>(n, NB);
    fill_kernel<<<(E + 255) / 256, 256>>>(edge, E);

    // ---- GIN layer 0 ----
    gather0_kernel<<<(n + 255) / 256, 256>>>(l0_eps, l0_b1, n);
    mmagemm0_kernel<<<NT, 256, SMEM_GEMM128>>>(agg, l0_w2, l0_b2, ybuf, sumv + 0, sqv + 0, n);
    bnapply_kernel<<<((size_t)n * 16 + 255) / 256, 256>>>(ybuf, sumv + 0, sqv + 0, bn0_g, bn0_b, XC, n);

    // ---- GIN layer 1: fp16 gather + MLP ----
    gather1_kernel<<<((size_t)((n + 1) / 2) * 32 + 255) / 256, 256>>>(l1_eps, n);
    mmamlp1_kernel<<<NT, 256, SMEM_MLP>>>(agg, l1_w1, l1_b1, l1_w2, l1_b2, ybuf, sumv + 64, sqv + 64, n);

    // ---- head: fused BN1-apply + code rowbias ----
    headgemm_kernel<<<NT, 256, SMEM_GEMM128>>>(XC, ybuf, fc_w1 + 128 * 64,
                                               sumv + 64, sqv + 64, bn1_g, bn1_b, fc_b1,
                                               ybuf, sumv + 128, sqv + 128, n);
    head_kernel<<<((size_t)n * 32 + 255) / 256, 256>>>(ybuf, sumv + 128, sqv + 128,
                                                       fc_bn_g, fc_bn_b, fc_w2, fc_b2, (float*)d_out, n);
}

// round 13
// speedup vs baseline: 1.0271x; 1.0271x over previous
#include <cuda_runtime.h>
#include <cuda_bf16.h>
#include <cuda_fp16.h>
#include <math.h>
#include <stdint.h>

// ---------------- problem constants ----------------
#define NMAX 100000
#define EMAX 1200000

// ---------------- device scratch ----------------
__device__ float d_XC[(size_t)NMAX * 64];        // h1 (fp32, for head)
__device__ __half d_XCh[(size_t)NMAX * 64];      // h1 (fp16, for gather1)
__device__ float d_agg[(size_t)NMAX * 128];      // gather output
__device__ float d_ybuf[(size_t)NMAX * 64];      // pre-BN output (reused)
__device__ float d_Tdeg[65 * 128];
__device__ float d_Tlab[16 * 128];
__device__ float d_Fdeg[65 * 64];
__device__ float d_Flab[16 * 64];
__device__ int   d_code[NMAX];
__device__ int   d_cnt[NMAX];
__device__ int   d_cursor[NMAX];
__device__ int   d_rowstart[NMAX + 1];
__device__ int   d_col[EMAX];
__device__ int   d_bsum[128];
__device__ float d_sum[3 * 64];
__device__ float d_sq[3 * 64];

__device__ __forceinline__ float lrelu(float x) { return x > 0.f ? x : 0.01f * x; }

__device__ __forceinline__ float to_tf32(float x) {
    float r;
    asm("cvt.rna.tf32.f32 %0, %1;" : "=f"(r) : "f"(x));
    return r;
}

// mma.sync m16n8k8 tf32: D += A(16x8) * B(8x8), fp32 accumulate
__device__ __forceinline__ void mma_tf32(float (&d)[4], const uint32_t (&a)[4], const uint32_t (&b)[2]) {
    asm volatile("mma.sync.aligned.m16n8k8.row.col.f32.tf32.tf32.f32 "
        "{%0,%1,%2,%3}, {%4,%5,%6,%7}, {%8,%9}, {%0,%1,%2,%3};"
        : "+f"(d[0]), "+f"(d[1]), "+f"(d[2]), "+f"(d[3])
        : "r"(a[0]), "r"(a[1]), "r"(a[2]), "r"(a[3]), "r"(b[0]), "r"(b[1]));
}

// ---------------- init (zero + code pack) and dictionary tables, merged ----------------
__global__ void zero_tables_kernel(const int* __restrict__ deg, const int* __restrict__ lab,
                                   const float* __restrict__ emb_deg,
                                   const float* __restrict__ emb_lab,
                                   const float* __restrict__ l0_w1,
                                   const float* __restrict__ fc_w1,
                                   int n, int nz) {
    __shared__ float e[64];
    int t = threadIdx.x;
    if ((int)blockIdx.x < nz) {
        int i = blockIdx.x * 256 + t;
        if (i < n) {
            d_cnt[i] = 0;
            d_code[i] = (deg[i] << 4) | lab[i];
        }
        if (i < 192) { d_sum[i] = 0.f; d_sq[i] = 0.f; }
        return;
    }
    int b = blockIdx.x - nz;
    const float* erow; const float* w; float* out; int H;
    if (b < 65)       { erow = emb_deg + b * 64;         w = l0_w1;            out = d_Tdeg + b * 128;         H = 128; }
    else if (b < 81)  { erow = emb_lab + (b - 65) * 64;  w = l0_w1 + 64 * 128; out = d_Tlab + (b - 65) * 128;  H = 128; }
    else if (b < 146) { erow = emb_deg + (b - 81) * 64;  w = fc_w1;            out = d_Fdeg + (b - 81) * 64;   H = 64;  }
    else              { erow = emb_lab + (b - 146) * 64; w = fc_w1 + 64 * 64;  out = d_Flab + (b - 146) * 64;  H = 64;  }
    if (t < 64) e[t] = erow[t];
    __syncthreads();
    if (t < H) {
        float s = 0.f;
        #pragma unroll 8
        for (int k = 0; k < 64; k++) s += e[k] * w[k * H + t];
        out[t] = s;
    }
}

// ---------------- CSR build ----------------
__global__ void count_kernel(const int* __restrict__ edge, int e) {
    int i = blockIdx.x * blockDim.x + threadIdx.x;
    if (i < e) atomicAdd(&d_cnt[edge[e + i]], 1);
}

__global__ void scanA_kernel(int n) {
    __shared__ int wsum[32];
    int t = threadIdx.x;
    int idx = blockIdx.x * 1024 + t;
    int v = (idx < n) ? d_cnt[idx] : 0;
    #pragma unroll
    for (int o = 16; o; o >>= 1) v += __shfl_xor_sync(0xffffffffu, v, o);
    if ((t & 31) == 0) wsum[t >> 5] = v;
    __syncthreads();
    if (t < 32) {
        int s = wsum[t];
        #pragma unroll
        for (int o = 16; o; o >>= 1) s += __shfl_xor_sync(0xffffffffu, s, o);
        if (t == 0) d_bsum[blockIdx.x] = s;
    }
}

// scanC with integrated block-offset scan; also initializes cursor = rowstart
__global__ void scanC_kernel(int n, int nb) {
    __shared__ int wsum[32];
    __shared__ int sb[128];
    int t = threadIdx.x;
    if (t < 128) sb[t] = (t < nb) ? d_bsum[t] : 0;
    __syncthreads();
    #pragma unroll
    for (int o = 1; o < 128; o <<= 1) {
        int u = (t < 128 && t >= o) ? sb[t - o] : 0;
        __syncthreads();
        if (t < 128) sb[t] += u;
        __syncthreads();
    }
    int boff = (blockIdx.x == 0) ? 0 : sb[blockIdx.x - 1];
    if (blockIdx.x == 0 && t == 0) d_rowstart[n] = sb[nb - 1];

    int idx = blockIdx.x * 1024 + t;
    int v = (idx < n) ? d_cnt[idx] : 0;
    int lane = t & 31, wid = t >> 5;
    int inc = v;
    #pragma unroll
    for (int o = 1; o < 32; o <<= 1) {
        int u = __shfl_up_sync(0xffffffffu, inc, o);
        if (lane >= o) inc += u;
    }
    if (lane == 31) wsum[wid] = inc;
    __syncthreads();
    if (t < 32) {
        int s = wsum[t];
        int sInc = s;
        #pragma unroll
        for (int o = 1; o < 32; o <<= 1) {
            int u = __shfl_up_sync(0xffffffffu, sInc, o);
            if (t >= o) sInc += u;
        }
        wsum[t] = sInc - s;
    }
    __syncthreads();
    if (idx < n) {
        int rs = boff + wsum[wid] + inc - v;
        d_rowstart[idx] = rs;
        d_cursor[idx] = rs;
    }
}

__global__ void fill_kernel(const int* __restrict__ edge, int e) {
    int i = blockIdx.x * blockDim.x + threadIdx.x;
    if (i < e) {
        int d = edge[e + i];
        int p = atomicAdd(&d_cursor[d], 1);
        d_col[p] = edge[i];
    }
}

// ---------------- layer-0 aggregation from fp32 smem dictionary tables ----------------
__global__ void __launch_bounds__(256)
gather0_kernel(const float* __restrict__ epsp, const float* __restrict__ b1, int n) {
    __shared__ __align__(16) float sTd[65 * 128];
    __shared__ __align__(16) float sTl[16 * 128];
    int t = threadIdx.x;
    {
        const float4* src = (const float4*)d_Tdeg;
        float4* dst = (float4*)sTd;
        for (int j = t; j < 65 * 32; j += 256) dst[j] = src[j];
        const float4* src2 = (const float4*)d_Tlab;
        float4* dst2 = (float4*)sTl;
        for (int j = t; j < 16 * 32; j += 256) dst2[j] = src2[j];
    }
    __syncthreads();
    const float4* Td4 = (const float4*)sTd;
    const float4* Tl4 = (const float4*)sTl;
    int lane = t & 31, w = t >> 5;
    int c = lane;
    float e1 = 1.0f + epsp[0];
    float4 b4 = ((const float4*)b1)[c];
    int base_node = blockIdx.x * 256 + w * 32;
    for (int it = 0; it < 32; it++) {
        int i = base_node + it;
        if (i >= n) break;
        int js = d_rowstart[i], je = d_rowstart[i + 1];
        int self = d_code[i];
        float4 a = Td4[(self >> 4) * 32 + c];
        float4 bsl = Tl4[(self & 15) * 32 + c];
        float4 s = make_float4(e1 * (a.x + bsl.x), e1 * (a.y + bsl.y),
                               e1 * (a.z + bsl.z), e1 * (a.w + bsl.w));
        for (int bs = js; bs < je; bs += 32) {
            int idx = bs + lane;
            int code = (idx < je) ? d_code[d_col[idx]] : 0;
            int m = min(32, je - bs);
            for (int j = 0; j < m; j++) {
                int cd = __shfl_sync(0xffffffffu, code, j);
                float4 u = Td4[(cd >> 4) * 32 + c];
                float4 v = Tl4[(cd & 15) * 32 + c];
                s.x += u.x + v.x; s.y += u.y + v.y;
                s.z += u.z + v.z; s.w += u.w + v.w;
            }
        }
        s.x = lrelu(s.x + b4.x); s.y = lrelu(s.y + b4.y);
        s.z = lrelu(s.z + b4.z); s.w = lrelu(s.w + b4.w);
        ((float4*)d_agg)[(size_t)i * 32 + c] = s;
    }
}

// ---------------- layer-1 aggregation (fp16 source, fp32 accumulate, 2-way MLP) ----------------
__global__ void gather1_kernel(const float* __restrict__ epsp, int n) {
    int lane = threadIdx.x & 31;
    int warp = (blockIdx.x * blockDim.x + threadIdx.x) >> 5;
    int i = warp * 2 + (lane >> 4);
    int c = lane & 15;
    if (i >= n) return;
    float e1 = 1.0f + epsp[0];
    const uint2* hb2 = (const uint2*)d_XCh;   // row = 16 uint2 (4 halves each)
    uint2 raw = hb2[(size_t)i * 16 + c];
    float2 a01 = __half22float2(*(const __half2*)&raw.x);
    float2 a23 = __half22float2(*(const __half2*)&raw.y);
    float4 s  = make_float4(a01.x * e1, a01.y * e1, a23.x * e1, a23.y * e1);
    float4 s2 = make_float4(0.f, 0.f, 0.f, 0.f);
    int js = d_rowstart[i], je = d_rowstart[i + 1];
    int j = js;
    for (; j + 1 < je; j += 2) {
        int n0 = d_col[j], n1 = d_col[j + 1];
        uint2 r0 = hb2[(size_t)n0 * 16 + c];
        uint2 r1 = hb2[(size_t)n1 * 16 + c];
        float2 u01 = __half22float2(*(const __half2*)&r0.x);
        float2 u23 = __half22float2(*(const __half2*)&r0.y);
        float2 v01 = __half22float2(*(const __half2*)&r1.x);
        float2 v23 = __half22float2(*(const __half2*)&r1.y);
        s.x  += u01.x; s.y  += u01.y; s.z  += u23.x; s.w  += u23.y;
        s2.x += v01.x; s2.y += v01.y; s2.z += v23.x; s2.w += v23.y;
    }
    if (j < je) {
        uint2 r = hb2[(size_t)d_col[j] * 16 + c];
        float2 u01 = __half22float2(*(const __half2*)&r.x);
        float2 u23 = __half22float2(*(const __half2*)&r.y);
        s.x += u01.x; s.y += u01.y; s.z += u23.x; s.w += u23.y;
    }
    s.x += s2.x; s.y += s2.y; s.z += s2.z; s.w += s2.w;
    ((float4*)d_agg)[(size_t)i * 16 + c] = s;
}

// ================= warp-level tf32 MMA GEMM building blocks =================
template <int K>
__device__ __forceinline__ void loadA_mma(float* xs, const float* __restrict__ x,
                                          int node0, int n, int t) {
    constexpr int KP = K + 4;
    int r = t >> 1;
    int cb = (t & 1) * (K / 2);
    int gn = node0 + r;
    const float4* src = (const float4*)(x + (size_t)gn * K + cb);
    #pragma unroll
    for (int i = 0; i < K / 8; i++) {
        float4 v = (gn < n) ? src[i] : make_float4(0.f, 0.f, 0.f, 0.f);
        float* dst = xs + r * KP + cb + i * 4;
        dst[0] = to_tf32(v.x); dst[1] = to_tf32(v.y);
        dst[2] = to_tf32(v.z); dst[3] = to_tf32(v.w);
    }
}

template <int K>
__device__ __forceinline__ void loadB_mma(float* wsT, const float* __restrict__ w, int t) {
    constexpr int KP = K + 4;
    #pragma unroll
    for (int i = 0; i < K * 64 / 256; i++) {
        int idx = t + i * 256;
        int k = idx >> 6, nn = idx & 63;
        wsT[nn * KP + k] = to_tf32(w[idx]);
    }
}

template <int K>
__device__ __forceinline__ void warp_mma(float (&acc)[8][4], const float* xs, const float* wsT,
                                         int rbase, int g, int tig) {
    constexpr int KP = K + 4;
    const float* xr0 = xs + (rbase + g) * KP;
    const float* xr1 = xs + (rbase + g + 8) * KP;
    #pragma unroll
    for (int ks = 0; ks < K / 8; ks++) {
        int k0 = ks * 8;
        uint32_t a[4];
        a[0] = __float_as_uint(xr0[k0 + tig]);
        a[1] = __float_as_uint(xr1[k0 + tig]);
        a[2] = __float_as_uint(xr0[k0 + tig + 4]);
        a[3] = __float_as_uint(xr1[k0 + tig + 4]);
        #pragma unroll
        for (int nt = 0; nt < 8; nt++) {
            const float* wr = wsT + (nt * 8 + g) * KP;
            uint32_t b[2];
            b[0] = __float_as_uint(wr[k0 + tig]);
            b[1] = __float_as_uint(wr[k0 + 4 + tig]);
            mma_tf32(acc[nt], a, b);
        }
    }
}

// stats + store epilogue
__device__ __forceinline__ void mma_store_stats(float (&acc)[8][4],
                                                const float2 (&bb0)[8], const float2 (&bb1)[8],
                                                int r0, int r1, bool v0, bool v1, int tig, int lane,
                                                float* __restrict__ y, float* csum, float* csq) {
    float ps[8][2], pq[8][2];
    #pragma unroll
    for (int nt = 0; nt < 8; nt++) {
        int c = nt * 8 + 2 * tig;
        float v00 = acc[nt][0] + bb0[nt].x, v01 = acc[nt][1] + bb0[nt].y;
        float v10 = acc[nt][2] + bb1[nt].x, v11 = acc[nt][3] + bb1[nt].y;
        float s0 = 0.f, s1 = 0.f, q0 = 0.f, q1 = 0.f;
        if (v0) { s0 += v00; s1 += v01; q0 += v00 * v00; q1 += v01 * v01; }
        if (v1) { s0 += v10; s1 += v11; q0 += v10 * v10; q1 += v11 * v11; }
        ps[nt][0] = s0; ps[nt][1] = s1; pq[nt][0] = q0; pq[nt][1] = q1;
        if (v0) *(float2*)(y + (size_t)r0 * 64 + c) = make_float2(v00, v01);
        if (v1) *(float2*)(y + (size_t)r1 * 64 + c) = make_float2(v10, v11);
    }
    #pragma unroll
    for (int o = 4; o <= 16; o <<= 1) {
        #pragma unroll
        for (int nt = 0; nt < 8; nt++) {
            ps[nt][0] += __shfl_xor_sync(0xffffffffu, ps[nt][0], o);
            ps[nt][1] += __shfl_xor_sync(0xffffffffu, ps[nt][1], o);
            pq[nt][0] += __shfl_xor_sync(0xffffffffu, pq[nt][0], o);
            pq[nt][1] += __shfl_xor_sync(0xffffffffu, pq[nt][1], o);
        }
    }
    if (lane < 4) {
        #pragma unroll
        for (int nt = 0; nt < 8; nt++) {
            int c = nt * 8 + 2 * tig;
            atomicAdd(&csum[c], ps[nt][0]);
            atomicAdd(&csum[c + 1], ps[nt][1]);
            atomicAdd(&csq[c], pq[nt][0]);
            atomicAdd(&csq[c + 1], pq[nt][1]);
        }
    }
}

// ---------------- layer-0 GEMM: y = agg[tile,128] @ w[128,64] + b ----------------
__global__ void __launch_bounds__(256, 2)
mmagemm0_kernel(const float* __restrict__ x, const float* __restrict__ w,
                const float* __restrict__ bias, float* __restrict__ y,
                float* __restrict__ gsum, float* __restrict__ gsq, int n) {
    constexpr int K = 128, KP = K + 4;
    extern __shared__ float sm[];
    float* xs  = sm;
    float* wsT = sm + 128 * KP;
    __shared__ float csum[64], csq[64];

    const int t = threadIdx.x;
    const int lane = t & 31, warp = t >> 5;
    const int g = lane >> 2, tig = lane & 3;
    const int rbase = warp * 16;
    const int node0 = blockIdx.x * 128;

    if (t < 64) { csum[t] = 0.f; csq[t] = 0.f; }
    loadA_mma<K>(xs, x, node0, n, t);
    loadB_mma<K>(wsT, w, t);
    __syncthreads();

    float acc[8][4];
    #pragma unroll
    for (int nt = 0; nt < 8; nt++)
        #pragma unroll
        for (int j = 0; j < 4; j++) acc[nt][j] = 0.f;
    warp_mma<K>(acc, xs, wsT, rbase, g, tig);

    int r0 = node0 + rbase + g, r1 = r0 + 8;
    bool v0 = r0 < n, v1 = r1 < n;
    float2 bb0[8], bb1[8];
    #pragma unroll
    for (int nt = 0; nt < 8; nt++) {
        float2 b2v = *(const float2*)(bias + nt * 8 + 2 * tig);
        bb0[nt] = b2v; bb1[nt] = b2v;
    }
    mma_store_stats(acc, bb0, bb1, r0, r1, v0, v1, tig, lane, y, csum, csq);

    __syncthreads();
    if (t < 64) {
        atomicAdd(&gsum[t], csum[t]);
        atomicAdd(&gsq[t], csq[t]);
    }
}

// ---------------- layer-1 MLP (tf32 MMA): y = lrelu(x@w1+b1)@w2+b2, stats ----------------
__global__ void __launch_bounds__(256, 2)
mmamlp1_kernel(const float* __restrict__ x,
               const float* __restrict__ w1, const float* __restrict__ b1,
               const float* __restrict__ w2, const float* __restrict__ b2,
               float* __restrict__ y,
               float* __restrict__ gsum, float* __restrict__ gsq, int n) {
    constexpr int K = 64, KP = K + 4;
    extern __shared__ float sm[];
    float* xs   = sm;                  // 128 * KP (reused for hidden)
    float* ws1T = sm + 128 * KP;
    float* ws2T = ws1T + 64 * KP;
    __shared__ float csum[64], csq[64];

    const int t = threadIdx.x;
    const int lane = t & 31, warp = t >> 5;
    const int g = lane >> 2, tig = lane & 3;
    const int rbase = warp * 16;
    const int node0 = blockIdx.x * 128;

    if (t < 64) { csum[t] = 0.f; csq[t] = 0.f; }
    loadA_mma<K>(xs, x, node0, n, t);
    loadB_mma<K>(ws1T, w1, t);
    loadB_mma<K>(ws2T, w2, t);
    __syncthreads();

    float acc[8][4];
    #pragma unroll
    for (int nt = 0; nt < 8; nt++)
        #pragma unroll
        for (int j = 0; j < 4; j++) acc[nt][j] = 0.f;

    // stage 1: hidden = lrelu(x @ w1 + b1) -> own xs rows
    warp_mma<K>(acc, xs, ws1T, rbase, g, tig);
    __syncwarp();
    {
        float* xr0 = xs + (rbase + g) * KP;
        float* xr1 = xs + (rbase + g + 8) * KP;
        #pragma unroll
        for (int nt = 0; nt < 8; nt++) {
            int c = nt * 8 + 2 * tig;
            float2 bb = *(const float2*)(b1 + c);
            xr0[c]     = to_tf32(lrelu(acc[nt][0] + bb.x));
            xr0[c + 1] = to_tf32(lrelu(acc[nt][1] + bb.y));
            xr1[c]     = to_tf32(lrelu(acc[nt][2] + bb.x));
            xr1[c + 1] = to_tf32(lrelu(acc[nt][3] + bb.y));
        }
    }
    __syncwarp();

    #pragma unroll
    for (int nt = 0; nt < 8; nt++)
        #pragma unroll
        for (int j = 0; j < 4; j++) acc[nt][j] = 0.f;

    // stage 2: y = hidden @ w2 + b2
    warp_mma<K>(acc, xs, ws2T, rbase, g, tig);

    int r0 = node0 + rbase + g, r1 = r0 + 8;
    bool v0 = r0 < n, v1 = r1 < n;
    float2 bb0[8], bb1[8];
    #pragma unroll
    for (int nt = 0; nt < 8; nt++) {
        float2 b2v = *(const float2*)(b2 + nt * 8 + 2 * tig);
        bb0[nt] = b2v; bb1[nt] = b2v;
    }
    mma_store_stats(acc, bb0, bb1, r0, r1, v0, v1, tig, lane, y, csum, csq);

    __syncthreads();
    if (t < 64) {
        atomicAdd(&gsum[t], csum[t]);
        atomicAdd(&gsq[t], csq[t]);
    }
}

// ---------------- head GEMM: fused BN1-apply on A-load + code rowbias epilogue ----------------
__global__ void __launch_bounds__(256, 2)
headgemm_kernel(const float* __restrict__ XC, const float* __restrict__ ybuf_in,
                const float* __restrict__ w,
                const float* __restrict__ gsum1, const float* __restrict__ gsq1,
                const float* __restrict__ bn1g, const float* __restrict__ bn1b,
                const float* __restrict__ fc_b1,
                float* __restrict__ y,
                float* __restrict__ gsum, float* __restrict__ gsq, int n) {
    constexpr int K = 128, KP = K + 4;
    extern __shared__ float sm[];
    float* xs  = sm;
    float* wsT = sm + 128 * KP;
    __shared__ float csum[64], csq[64], sc[64], sh[64];

    const int t = threadIdx.x;
    const int lane = t & 31, warp = t >> 5;
    const int g = lane >> 2, tig = lane & 3;
    const int rbase = warp * 16;
    const int node0 = blockIdx.x * 128;

    if (t < 64) {
        csum[t] = 0.f; csq[t] = 0.f;
        float invn = 1.0f / (float)n;
        float m = gsum1[t] * invn;
        float var = gsq1[t] * invn - m * m;
        float s = bn1g[t] * rsqrtf(var + 1e-5f);
        sc[t] = s; sh[t] = bn1b[t] - m * s;
    }
    __syncthreads();

    loadB_mma<K>(wsT, w, t);
    // A tile: cols 0..63 = h1 (XC), cols 64..127 = h2 = lrelu(bn1(ybuf))
    {
        int r = t >> 1;
        int gn = node0 + r;
        if ((t & 1) == 0) {
            const float4* src = (const float4*)(XC + (size_t)gn * 64);
            float* dst = xs + r * KP;
            #pragma unroll
            for (int i = 0; i < 16; i++) {
                float4 v = (gn < n) ? src[i] : make_float4(0.f, 0.f, 0.f, 0.f);
                dst[i * 4 + 0] = to_tf32(v.x); dst[i * 4 + 1] = to_tf32(v.y);
                dst[i * 4 + 2] = to_tf32(v.z); dst[i * 4 + 3] = to_tf32(v.w);
            }
        } else {
            const float4* src = (const float4*)(ybuf_in + (size_t)gn * 64);
            float* dst = xs + r * KP + 64;
            #pragma unroll
            for (int i = 0; i < 16; i++) {
                float4 v = (gn < n) ? src[i] : make_float4(0.f, 0.f, 0.f, 0.f);
                int c = i * 4;
                dst[c + 0] = to_tf32(lrelu(v.x * sc[c + 0] + sh[c + 0]));
                dst[c + 1] = to_tf32(lrelu(v.y * sc[c + 1] + sh[c + 1]));
                dst[c + 2] = to_tf32(lrelu(v.z * sc[c + 2] + sh[c + 2]));
                dst[c + 3] = to_tf32(lrelu(v.w * sc[c + 3] + sh[c + 3]));
            }
        }
    }
    __syncthreads();

    float acc[8][4];
    #pragma unroll
    for (int nt = 0; nt < 8; nt++)
        #pragma unroll
        for (int j = 0; j < 4; j++) acc[nt][j] = 0.f;
    warp_mma<K>(acc, xs, wsT, rbase, g, tig);

    int r0 = node0 + rbase + g, r1 = r0 + 8;
    bool v0 = r0 < n, v1 = r1 < n;
    int code0 = v0 ? d_code[r0] : 0;
    int code1 = v1 ? d_code[r1] : 0;
    const float* fd0 = d_Fdeg + (code0 >> 4) * 64;
    const float* fl0 = d_Flab + (code0 & 15) * 64;
    const float* fd1 = d_Fdeg + (code1 >> 4) * 64;
    const float* fl1 = d_Flab + (code1 & 15) * 64;
    float2 bb0[8], bb1[8];
    #pragma unroll
    for (int nt = 0; nt < 8; nt++) {
        int c = nt * 8 + 2 * tig;
        float2 fb = *(const float2*)(fc_b1 + c);
        float2 a0 = *(const float2*)(fd0 + c);
        float2 l0 = *(const float2*)(fl0 + c);
        float2 a1 = *(const float2*)(fd1 + c);
        float2 l1 = *(const float2*)(fl1 + c);
        bb0[nt] = make_float2(a0.x + l0.x + fb.x, a0.y + l0.y + fb.y);
        bb1[nt] = make_float2(a1.x + l1.x + fb.x, a1.y + l1.y + fb.y);
    }
    mma_store_stats(acc, bb0, bb1, r0, r1, v0, v1, tig, lane, y, csum, csq);

    __syncthreads();
    if (t < 64) {
        atomicAdd(&gsum[t], csum[t]);
        atomicAdd(&gsq[t], csq[t]);
    }
}

// ---------------- BN apply + lrelu (layer 0): writes fp32 XC + fp16 XCh ----------------
__global__ void bnapply_kernel(const float* __restrict__ y,
                               const float* __restrict__ gsum, const float* __restrict__ gsq,
                               const float* __restrict__ g, const float* __restrict__ b,
                               float* __restrict__ out, int n) {
    __shared__ float sc[64], sh[64];
    int t = threadIdx.x;
    if (t < 64) {
        float invn = 1.0f / (float)n;
        float m = gsum[t] * invn;
        float var = gsq[t] * invn - m * m;
        float s = g[t] * rsqrtf(var + 1e-5f);
        sc[t] = s; sh[t] = b[t] - m * s;
    }
    __syncthreads();
    int idx = blockIdx.x * blockDim.x + t;
    int i = idx >> 4, c = idx & 15;
    if (i >= n) return;
    float4 v = ((const float4*)y)[(size_t)i * 16 + c];
    v.x = lrelu(v.x * sc[c * 4 + 0] + sh[c * 4 + 0]);
    v.y = lrelu(v.y * sc[c * 4 + 1] + sh[c * 4 + 1]);
    v.z = lrelu(v.z * sc[c * 4 + 2] + sh[c * 4 + 2]);
    v.w = lrelu(v.w * sc[c * 4 + 3] + sh[c * 4 + 3]);
    ((float4*)out)[(size_t)i * 16 + c] = v;
    // fp16 copy for gather1
    uint2 pk;
    __half2 p0 = __floats2half2_rn(v.x, v.y);
    __half2 p1 = __floats2half2_rn(v.z, v.w);
    pk.x = *(const uint32_t*)&p0;
    pk.y = *(const uint32_t*)&p1;
    ((uint2*)d_XCh)[(size_t)i * 16 + c] = pk;
}

// ---------------- head: lrelu(bn(y)) @ fc_w2 + b2 -> sigmoid ----------------
__global__ void head_kernel(const float* __restrict__ y,
                            const float* __restrict__ gsum, const float* __restrict__ gsq,
                            const float* __restrict__ g, const float* __restrict__ b,
                            const float* __restrict__ w2, const float* __restrict__ b2,
                            float* __restrict__ out, int n) {
    __shared__ float sc[64], sh[64];
    int t = threadIdx.x;
    if (t < 64) {
        float invn = 1.0f / (float)n;
        float m = gsum[t] * invn;
        float var = gsq[t] * invn - m * m;
        float s = g[t] * rsqrtf(var + 1e-5f);
        sc[t] = s; sh[t] = b[t] - m * s;
    }
    __syncthreads();
    int lane = t & 31;
    int i = (blockIdx.x * blockDim.x + t) >> 5;
    if (i >= n) return;
    float2 v = ((const float2*)y)[(size_t)i * 32 + lane];
    float z0 = lrelu(v.x * sc[2 * lane] + sh[2 * lane]);
    float z1 = lrelu(v.y * sc[2 * lane + 1] + sh[2 * lane + 1]);
    float a = z0 * w2[2 * lane] + z1 * w2[2 * lane + 1];
    #pragma unroll
    for (int o = 16; o; o >>= 1) a += __shfl_xor_sync(0xffffffffu, a, o);
    if (lane == 0) out[i] = 1.0f / (1.0f + expf(-(a + b2[0])));
}

// ---------------- launch ----------------
extern "C" void kernel_launch(void* const* d_in, const int* in_sizes, int n_in,
                              void* d_out, int out_size) {
    const int*   node_deg = (const int*)d_in[0];
    const int*   node_lab = (const int*)d_in[1];
    const int*   edge     = (const int*)d_in[2];
    const float* emb_deg  = (const float*)d_in[3];
    const float* emb_lab  = (const float*)d_in[4];
    const float* l0_w1 = (const float*)d_in[5];
    const float* l0_b1 = (const float*)d_in[6];
    const float* l0_w2 = (const float*)d_in[7];
    const float* l0_b2 = (const float*)d_in[8];
    const float* l0_eps = (const float*)d_in[9];
    const float* bn0_g = (const float*)d_in[10];
    const float* bn0_b = (const float*)d_in[11];
    const float* l1_w1 = (const float*)d_in[12];
    const float* l1_b1 = (const float*)d_in[13];
    const float* l1_w2 = (const float*)d_in[14];
    const float* l1_b2 = (const float*)d_in[15];
    const float* l1_eps = (const float*)d_in[16];
    const float* bn1_g = (const float*)d_in[17];
    const float* bn1_b = (const float*)d_in[18];
    const float* fc_w1 = (const float*)d_in[19];
    const float* fc_b1 = (const float*)d_in[20];
    const float* fc_bn_g = (const float*)d_in[21];
    const float* fc_bn_b = (const float*)d_in[22];
    const float* fc_w2 = (const float*)d_in[23];
    const float* fc_b2 = (const float*)d_in[24];

    int n = in_sizes[0];
    int E = in_sizes[2] / 2;

    float *XC, *agg, *ybuf, *sumv, *sqv;
    cudaGetSymbolAddress((void**)&XC,   d_XC);
    cudaGetSymbolAddress((void**)&agg,  d_agg);
    cudaGetSymbolAddress((void**)&ybuf, d_ybuf);
    cudaGetSymbolAddress((void**)&sumv, d_sum);
    cudaGetSymbolAddress((void**)&sqv,  d_sq);

    const int SMEM_GEMM128 = (128 + 64) * (128 + 4) * 4;       // 101376
    const int SMEM_MLP     = (128 + 64 + 64) * (64 + 4) * 4;   // 69632
    cudaFuncSetAttribute(mmagemm0_kernel, cudaFuncAttributeMaxDynamicSharedMemorySize, SMEM_GEMM128);
    cudaFuncSetAttribute(headgemm_kernel, cudaFuncAttributeMaxDynamicSharedMemorySize, SMEM_GEMM128);
    cudaFuncSetAttribute(mmamlp1_kernel,  cudaFuncAttributeMaxDynamicSharedMemorySize, SMEM_MLP);

    int NB = (n + 1023) / 1024;
    int NZ = (n + 255) / 256;
    int NT = (n + 127) / 128;

    // init (+tables) + CSR build
    zero_tables_kernel<<<NZ + 162, 256>>>(node_deg, node_lab, emb_deg, emb_lab, l0_w1, fc_w1, n, NZ);
    count_kernel<<<(E + 255) / 256, 256>>>(edge, E);
    scanA_kernel<<<NB, 1024>>>(n);
    scanC_kernel<<<NB, 1024>>>(n, NB);
    fill_kernel<<<(E + 255) / 256, 256>>>(edge, E);

    // ---- GIN layer 0 ----
    gather0_kernel<<<(n + 255) / 256, 256>>>(l0_eps, l0_b1, n);
    mmagemm0_kernel<<<NT, 256, SMEM_GEMM128>>>(agg, l0_w2, l0_b2, ybuf, sumv + 0, sqv + 0, n);
    bnapply_kernel<<<((size_t)n * 16 + 255) / 256, 256>>>(ybuf, sumv + 0, sqv + 0, bn0_g, bn0_b, XC, n);

    // ---- GIN layer 1: fp16 gather (2-way unroll) + MLP ----
    gather1_kernel<<<((size_t)((n + 1) / 2) * 32 + 255) / 256, 256>>>(l1_eps, n);
    mmamlp1_kernel<<<NT, 256, SMEM_MLP>>>(agg, l1_w1, l1_b1, l1_w2, l1_b2, ybuf, sumv + 64, sqv + 64, n);

    // ---- head: fused BN1-apply + code rowbias ----
    headgemm_kernel<<<NT, 256, SMEM_GEMM128>>>(XC, ybuf, fc_w1 + 128 * 64,
                                               sumv + 64, sqv + 64, bn1_g, bn1_b, fc_b1,
                                               ybuf, sumv + 128, sqv + 128, n);
    head_kernel<<<((size_t)n * 32 + 255) / 256, 256>>>(ybuf, sumv + 128, sqv + 128,
                                                       fc_bn_g, fc_bn_b, fc_w2, fc_b2, (float*)d_out, n);
}

// round 14
// speedup vs baseline: 1.0819x; 1.0534x over previous
#include <cuda_runtime.h>
#include <cuda_bf16.h>
#include <cuda_fp16.h>
#include <math.h>
#include <stdint.h>

// ---------------- problem constants ----------------
#define NMAX 100000
#define EMAX 1200000

// ---------------- device scratch ----------------
__device__ float d_XC[(size_t)NMAX * 64];        // h1 (fp32, for head)
__device__ __half d_XCh[(size_t)NMAX * 64];      // h1 (fp16, for gather1)
__device__ float d_agg[(size_t)NMAX * 64];       // layer-1 gather output
__device__ float d_ybuf[(size_t)NMAX * 64];      // pre-BN output (reused)
__device__ float d_Tdeg[65 * 128];
__device__ float d_Tlab[16 * 128];
__device__ float d_Fdeg[65 * 64];
__device__ float d_Flab[16 * 64];
__device__ int   d_code[NMAX];
__device__ int   d_cnt[NMAX];
__device__ int   d_cursor[NMAX];
__device__ int   d_rowstart[NMAX + 1];
__device__ int   d_col[EMAX];          // packed: (code << 17) | src_id
__device__ int   d_bsum[128];
__device__ float d_sum[3 * 64];
__device__ float d_sq[3 * 64];

__device__ __forceinline__ float lrelu(float x) { return x > 0.f ? x : 0.01f * x; }

__device__ __forceinline__ float to_tf32(float x) {
    float r;
    asm("cvt.rna.tf32.f32 %0, %1;" : "=f"(r) : "f"(x));
    return r;
}

// mma.sync m16n8k8 tf32: D += A(16x8) * B(8x8), fp32 accumulate
__device__ __forceinline__ void mma_tf32(float (&d)[4], const uint32_t (&a)[4], const uint32_t (&b)[2]) {
    asm volatile("mma.sync.aligned.m16n8k8.row.col.f32.tf32.tf32.f32 "
        "{%0,%1,%2,%3}, {%4,%5,%6,%7}, {%8,%9}, {%0,%1,%2,%3};"
        : "+f"(d[0]), "+f"(d[1]), "+f"(d[2]), "+f"(d[3])
        : "r"(a[0]), "r"(a[1]), "r"(a[2]), "r"(a[3]), "r"(b[0]), "r"(b[1]));
}

// ---------------- init (zero + code pack) and dictionary tables, merged ----------------
__global__ void zero_tables_kernel(const int* __restrict__ deg, const int* __restrict__ lab,
                                   const float* __restrict__ emb_deg,
                                   const float* __restrict__ emb_lab,
                                   const float* __restrict__ l0_w1,
                                   const float* __restrict__ fc_w1,
                                   int n, int nz) {
    __shared__ float e[64];
    int t = threadIdx.x;
    if ((int)blockIdx.x < nz) {
        int i = blockIdx.x * 256 + t;
        if (i < n) {
            d_cnt[i] = 0;
            d_code[i] = (deg[i] << 4) | lab[i];
        }
        if (i < 192) { d_sum[i] = 0.f; d_sq[i] = 0.f; }
        return;
    }
    int b = blockIdx.x - nz;
    const float* erow; const float* w; float* out; int H;
    if (b < 65)       { erow = emb_deg + b * 64;         w = l0_w1;            out = d_Tdeg + b * 128;         H = 128; }
    else if (b < 81)  { erow = emb_lab + (b - 65) * 64;  w = l0_w1 + 64 * 128; out = d_Tlab + (b - 65) * 128;  H = 128; }
    else if (b < 146) { erow = emb_deg + (b - 81) * 64;  w = fc_w1;            out = d_Fdeg + (b - 81) * 64;   H = 64;  }
    else              { erow = emb_lab + (b - 146) * 64; w = fc_w1 + 64 * 64;  out = d_Flab + (b - 146) * 64;  H = 64;  }
    if (t < 64) e[t] = erow[t];
    __syncthreads();
    if (t < H) {
        float s = 0.f;
        #pragma unroll 8
        for (int k = 0; k < 64; k++) s += e[k] * w[k * H + t];
        out[t] = s;
    }
}

// ---------------- CSR build ----------------
__global__ void count_kernel(const int* __restrict__ edge, int e) {
    int i = blockIdx.x * blockDim.x + threadIdx.x;
    if (i < e) atomicAdd(&d_cnt[edge[e + i]], 1);
}

__global__ void scanA_kernel(int n) {
    __shared__ int wsum[32];
    int t = threadIdx.x;
    int idx = blockIdx.x * 1024 + t;
    int v = (idx < n) ? d_cnt[idx] : 0;
    #pragma unroll
    for (int o = 16; o; o >>= 1) v += __shfl_xor_sync(0xffffffffu, v, o);
    if ((t & 31) == 0) wsum[t >> 5] = v;
    __syncthreads();
    if (t < 32) {
        int s = wsum[t];
        #pragma unroll
        for (int o = 16; o; o >>= 1) s += __shfl_xor_sync(0xffffffffu, s, o);
        if (t == 0) d_bsum[blockIdx.x] = s;
    }
}

// scanC with integrated block-offset scan; also initializes cursor = rowstart
__global__ void scanC_kernel(int n, int nb) {
    __shared__ int wsum[32];
    __shared__ int sb[128];
    int t = threadIdx.x;
    if (t < 128) sb[t] = (t < nb) ? d_bsum[t] : 0;
    __syncthreads();
    #pragma unroll
    for (int o = 1; o < 128; o <<= 1) {
        int u = (t < 128 && t >= o) ? sb[t - o] : 0;
        __syncthreads();
        if (t < 128) sb[t] += u;
        __syncthreads();
    }
    int boff = (blockIdx.x == 0) ? 0 : sb[blockIdx.x - 1];
    if (blockIdx.x == 0 && t == 0) d_rowstart[n] = sb[nb - 1];

    int idx = blockIdx.x * 1024 + t;
    int v = (idx < n) ? d_cnt[idx] : 0;
    int lane = t & 31, wid = t >> 5;
    int inc = v;
    #pragma unroll
    for (int o = 1; o < 32; o <<= 1) {
        int u = __shfl_up_sync(0xffffffffu, inc, o);
        if (lane >= o) inc += u;
    }
    if (lane == 31) wsum[wid] = inc;
    __syncthreads();
    if (t < 32) {
        int s = wsum[t];
        int sInc = s;
        #pragma unroll
        for (int o = 1; o < 32; o <<= 1) {
            int u = __shfl_up_sync(0xffffffffu, sInc, o);
            if (t >= o) sInc += u;
        }
        wsum[t] = sInc - s;
    }
    __syncthreads();
    if (idx < n) {
        int rs = boff + wsum[wid] + inc - v;
        d_rowstart[idx] = rs;
        d_cursor[idx] = rs;
    }
}

// fill: pack neighbor code into high bits (id < 2^17, code 11 bits)
__global__ void fill_kernel(const int* __restrict__ edge, int e) {
    int i = blockIdx.x * blockDim.x + threadIdx.x;
    if (i < e) {
        int s = edge[i];
        int d = edge[e + i];
        int p = atomicAdd(&d_cursor[d], 1);
        d_col[p] = (d_code[s] << 17) | s;
    }
}

// ---------------- fused GIN layer 0 as count-GEMM ----------------
// C[128][88] counts (codes; k<65 = deg, 65..80 = lab), agg = C @ T (tf32 MMA),
// hidden = lrelu(agg + b1), y = hidden @ w2 + b2 (+stats)
__global__ void __launch_bounds__(256, 2)
gin0_kernel(const float* __restrict__ epsp, const float* __restrict__ b1,
            const float* __restrict__ w2, const float* __restrict__ b2,
            float* __restrict__ y,
            float* __restrict__ gsum, float* __restrict__ gsq, int n) {
    constexpr int KP1 = 92;    // 88 + 4 pad
    constexpr int KP2 = 132;   // 128 + 4 pad
    extern __shared__ float sm[];
    float* Cm = sm;                    // stage1 A: counts [128][92] (11776 floats)
    float* Ts = sm + 13568;            // stage1 B: table [128 cols][92]  (11776 floats, ends 25344)
    float* hid = sm;                   // stage2 A: hidden [128][132] (16896 floats)
    float* w2T = sm + 16896;           // stage2 B: [64][132] (8448 floats, ends 25344)
    __shared__ float csum[64], csq[64];

    const int t = threadIdx.x;
    const int lane = t & 31, warp = t >> 5;
    const int g = lane >> 2, tig = lane & 3;
    const int rbase = warp * 16;
    const int node0 = blockIdx.x * 128;

    if (t < 64) { csum[t] = 0.f; csq[t] = 0.f; }
    // zero C + load tf32 table (Ts[c*92+k] = T[k][c])
    for (int idx = t; idx < 128 * KP1; idx += 256) Cm[idx] = 0.f;
    for (int idx = t; idx < 128 * KP1; idx += 256) {
        int c = idx / KP1, k = idx - c * KP1;
        float v = 0.f;
        if (k < 65) v = d_Tdeg[k * 128 + c];
        else if (k < 81) v = d_Tlab[(k - 65) * 128 + c];
        Ts[idx] = to_tf32(v);
    }
    __syncthreads();

    // build counts: 2 threads per row, smem atomics
    {
        float e1 = 1.0f + epsp[0];
        int r = t >> 1, part = t & 1;
        int i = node0 + r;
        float* Crow = Cm + r * KP1;
        if (i < n) {
            if (part == 0) {
                int self = d_code[i];
                atomicAdd(&Crow[self >> 4], e1);
                atomicAdd(&Crow[65 + (self & 15)], e1);
            }
            int js = d_rowstart[i], je = d_rowstart[i + 1];
            for (int j = js + part; j < je; j += 2) {
                int cd = d_col[j] >> 17;
                atomicAdd(&Crow[cd >> 4], 1.0f);
                atomicAdd(&Crow[65 + (cd & 15)], 1.0f);
            }
        }
    }
    __syncthreads();

    // stage 1: agg(128 cols) = C @ T ; K=88, 11 ksteps, 16 ntiles
    float acc1[16][4];
    #pragma unroll
    for (int nt = 0; nt < 16; nt++)
        #pragma unroll
        for (int j = 0; j < 4; j++) acc1[nt][j] = 0.f;
    {
        const float* xr0 = Cm + (rbase + g) * KP1;
        const float* xr1 = Cm + (rbase + g + 8) * KP1;
        #pragma unroll
        for (int ks = 0; ks < 11; ks++) {
            int k0 = ks * 8;
            uint32_t a[4];
            a[0] = __float_as_uint(xr0[k0 + tig]);
            a[1] = __float_as_uint(xr1[k0 + tig]);
            a[2] = __float_as_uint(xr0[k0 + tig + 4]);
            a[3] = __float_as_uint(xr1[k0 + tig + 4]);
            #pragma unroll
            for (int nt = 0; nt < 16; nt++) {
                const float* wr = Ts + (nt * 8 + g) * KP1;
                uint32_t b[2];
                b[0] = __float_as_uint(wr[k0 + tig]);
                b[1] = __float_as_uint(wr[k0 + 4 + tig]);
                mma_tf32(acc1[nt], a, b);
            }
        }
    }
    __syncthreads();   // C & Ts dead; smem reusable

    // hidden = tf32(lrelu(agg + b1)) -> hid; concurrently load w2T
    {
        float* h0 = hid + (rbase + g) * KP2;
        float* h1 = hid + (rbase + g + 8) * KP2;
        #pragma unroll
        for (int nt = 0; nt < 16; nt++) {
            int c = nt * 8 + 2 * tig;
            float2 bb = *(const float2*)(b1 + c);
            h0[c]     = to_tf32(lrelu(acc1[nt][0] + bb.x));
            h0[c + 1] = to_tf32(lrelu(acc1[nt][1] + bb.y));
            h1[c]     = to_tf32(lrelu(acc1[nt][2] + bb.x));
            h1[c + 1] = to_tf32(lrelu(acc1[nt][3] + bb.y));
        }
    }
    #pragma unroll
    for (int i = 0; i < 32; i++) {
        int idx = t + i * 256;
        int k = idx >> 6, nn = idx & 63;
        w2T[nn * KP2 + k] = to_tf32(w2[idx]);
    }
    __syncthreads();

    // stage 2: y = hidden @ w2 + b2 ; K=128, 8 ntiles
    float acc[8][4];
    #pragma unroll
    for (int nt = 0; nt < 8; nt++)
        #pragma unroll
        for (int j = 0; j < 4; j++) acc[nt][j] = 0.f;
    {
        const float* xr0 = hid + (rbase + g) * KP2;
        const float* xr1 = hid + (rbase + g + 8) * KP2;
        #pragma unroll
        for (int ks = 0; ks < 16; ks++) {
            int k0 = ks * 8;
            uint32_t a[4];
            a[0] = __float_as_uint(xr0[k0 + tig]);
            a[1] = __float_as_uint(xr1[k0 + tig]);
            a[2] = __float_as_uint(xr0[k0 + tig + 4]);
            a[3] = __float_as_uint(xr1[k0 + tig + 4]);
            #pragma unroll
            for (int nt = 0; nt < 8; nt++) {
                const float* wr = w2T + (nt * 8 + g) * KP2;
                uint32_t b[2];
                b[0] = __float_as_uint(wr[k0 + tig]);
                b[1] = __float_as_uint(wr[k0 + 4 + tig]);
                mma_tf32(acc[nt], a, b);
            }
        }
    }

    // epilogue: + b2, stats, store
    int r0 = node0 + rbase + g, r1 = r0 + 8;
    bool v0 = r0 < n, v1 = r1 < n;
    float ps[8][2], pq[8][2];
    #pragma unroll
    for (int nt = 0; nt < 8; nt++) {
        int c = nt * 8 + 2 * tig;
        float2 bb = *(const float2*)(b2 + c);
        float v00 = acc[nt][0] + bb.x, v01 = acc[nt][1] + bb.y;
        float v10 = acc[nt][2] + bb.x, v11 = acc[nt][3] + bb.y;
        float s0 = 0.f, s1 = 0.f, q0 = 0.f, q1 = 0.f;
        if (v0) { s0 += v00; s1 += v01; q0 += v00 * v00; q1 += v01 * v01; }
        if (v1) { s0 += v10; s1 += v11; q0 += v10 * v10; q1 += v11 * v11; }
        ps[nt][0] = s0; ps[nt][1] = s1; pq[nt][0] = q0; pq[nt][1] = q1;
        if (v0) *(float2*)(y + (size_t)r0 * 64 + c) = make_float2(v00, v01);
        if (v1) *(float2*)(y + (size_t)r1 * 64 + c) = make_float2(v10, v11);
    }
    #pragma unroll
    for (int o = 4; o <= 16; o <<= 1) {
        #pragma unroll
        for (int nt = 0; nt < 8; nt++) {
            ps[nt][0] += __shfl_xor_sync(0xffffffffu, ps[nt][0], o);
            ps[nt][1] += __shfl_xor_sync(0xffffffffu, ps[nt][1], o);
            pq[nt][0] += __shfl_xor_sync(0xffffffffu, pq[nt][0], o);
            pq[nt][1] += __shfl_xor_sync(0xffffffffu, pq[nt][1], o);
        }
    }
    if (lane < 4) {
        #pragma unroll
        for (int nt = 0; nt < 8; nt++) {
            int c = nt * 8 + 2 * tig;
            atomicAdd(&csum[c], ps[nt][0]);
            atomicAdd(&csum[c + 1], ps[nt][1]);
            atomicAdd(&csq[c], pq[nt][0]);
            atomicAdd(&csq[c + 1], pq[nt][1]);
        }
    }
    __syncthreads();
    if (t < 64) {
        atomicAdd(&gsum[t], csum[t]);
        atomicAdd(&gsq[t], csq[t]);
    }
}

// ---------------- layer-1 aggregation (fp16 source, fp32 accumulate) ----------------
__global__ void gather1_kernel(const float* __restrict__ epsp, int n) {
    int lane = threadIdx.x & 31;
    int warp = (blockIdx.x * blockDim.x + threadIdx.x) >> 5;
    int i = warp * 2 + (lane >> 4);
    int c = lane & 15;
    if (i >= n) return;
    float e1 = 1.0f + epsp[0];
    const uint2* hb2 = (const uint2*)d_XCh;
    uint2 raw = hb2[(size_t)i * 16 + c];
    float2 a01 = __half22float2(*(const __half2*)&raw.x);
    float2 a23 = __half22float2(*(const __half2*)&raw.y);
    float4 s = make_float4(a01.x * e1, a01.y * e1, a23.x * e1, a23.y * e1);
    int js = d_rowstart[i], je = d_rowstart[i + 1];
    for (int j = js; j < je; j++) {
        int nb = d_col[j] & 0x1FFFF;
        uint2 r = hb2[(size_t)nb * 16 + c];
        float2 v01 = __half22float2(*(const __half2*)&r.x);
        float2 v23 = __half22float2(*(const __half2*)&r.y);
        s.x += v01.x; s.y += v01.y; s.z += v23.x; s.w += v23.y;
    }
    ((float4*)d_agg)[(size_t)i * 16 + c] = s;
}

// ================= warp-level tf32 MMA GEMM building blocks =================
template <int K>
__device__ __forceinline__ void loadA_mma(float* xs, const float* __restrict__ x,
                                          int node0, int n, int t) {
    constexpr int KP = K + 4;
    int r = t >> 1;
    int cb = (t & 1) * (K / 2);
    int gn = node0 + r;
    const float4* src = (const float4*)(x + (size_t)gn * K + cb);
    #pragma unroll
    for (int i = 0; i < K / 8; i++) {
        float4 v = (gn < n) ? src[i] : make_float4(0.f, 0.f, 0.f, 0.f);
        float* dst = xs + r * KP + cb + i * 4;
        dst[0] = to_tf32(v.x); dst[1] = to_tf32(v.y);
        dst[2] = to_tf32(v.z); dst[3] = to_tf32(v.w);
    }
}

template <int K>
__device__ __forceinline__ void loadB_mma(float* wsT, const float* __restrict__ w, int t) {
    constexpr int KP = K + 4;
    #pragma unroll
    for (int i = 0; i < K * 64 / 256; i++) {
        int idx = t + i * 256;
        int k = idx >> 6, nn = idx & 63;
        wsT[nn * KP + k] = to_tf32(w[idx]);
    }
}

template <int K>
__device__ __forceinline__ void warp_mma(float (&acc)[8][4], const float* xs, const float* wsT,
                                         int rbase, int g, int tig) {
    constexpr int KP = K + 4;
    const float* xr0 = xs + (rbase + g) * KP;
    const float* xr1 = xs + (rbase + g + 8) * KP;
    #pragma unroll
    for (int ks = 0; ks < K / 8; ks++) {
        int k0 = ks * 8;
        uint32_t a[4];
        a[0] = __float_as_uint(xr0[k0 + tig]);
        a[1] = __float_as_uint(xr1[k0 + tig]);
        a[2] = __float_as_uint(xr0[k0 + tig + 4]);
        a[3] = __float_as_uint(xr1[k0 + tig + 4]);
        #pragma unroll
        for (int nt = 0; nt < 8; nt++) {
            const float* wr = wsT + (nt * 8 + g) * KP;
            uint32_t b[2];
            b[0] = __float_as_uint(wr[k0 + tig]);
            b[1] = __float_as_uint(wr[k0 + 4 + tig]);
            mma_tf32(acc[nt], a, b);
        }
    }
}

// stats + store epilogue
__device__ __forceinline__ void mma_store_stats(float (&acc)[8][4],
                                                const float2 (&bb0)[8], const float2 (&bb1)[8],
                                                int r0, int r1, bool v0, bool v1, int tig, int lane,
                                                float* __restrict__ y, float* csum, float* csq) {
    float ps[8][2], pq[8][2];
    #pragma unroll
    for (int nt = 0; nt < 8; nt++) {
        int c = nt * 8 + 2 * tig;
        float v00 = acc[nt][0] + bb0[nt].x, v01 = acc[nt][1] + bb0[nt].y;
        float v10 = acc[nt][2] + bb1[nt].x, v11 = acc[nt][3] + bb1[nt].y;
        float s0 = 0.f, s1 = 0.f, q0 = 0.f, q1 = 0.f;
        if (v0) { s0 += v00; s1 += v01; q0 += v00 * v00; q1 += v01 * v01; }
        if (v1) { s0 += v10; s1 += v11; q0 += v10 * v10; q1 += v11 * v11; }
        ps[nt][0] = s0; ps[nt][1] = s1; pq[nt][0] = q0; pq[nt][1] = q1;
        if (v0) *(float2*)(y + (size_t)r0 * 64 + c) = make_float2(v00, v01);
        if (v1) *(float2*)(y + (size_t)r1 * 64 + c) = make_float2(v10, v11);
    }
    #pragma unroll
    for (int o = 4; o <= 16; o <<= 1) {
        #pragma unroll
        for (int nt = 0; nt < 8; nt++) {
            ps[nt][0] += __shfl_xor_sync(0xffffffffu, ps[nt][0], o);
            ps[nt][1] += __shfl_xor_sync(0xffffffffu, ps[nt][1], o);
            pq[nt][0] += __shfl_xor_sync(0xffffffffu, pq[nt][0], o);
            pq[nt][1] += __shfl_xor_sync(0xffffffffu, pq[nt][1], o);
        }
    }
    if (lane < 4) {
        #pragma unroll
        for (int nt = 0; nt < 8; nt++) {
            int c = nt * 8 + 2 * tig;
            atomicAdd(&csum[c], ps[nt][0]);
            atomicAdd(&csum[c + 1], ps[nt][1]);
            atomicAdd(&csq[c], pq[nt][0]);
            atomicAdd(&csq[c + 1], pq[nt][1]);
        }
    }
}

// ---------------- layer-1 MLP (tf32 MMA): y = lrelu(x@w1+b1)@w2+b2, stats ----------------
__global__ void __launch_bounds__(256, 2)
mmamlp1_kernel(const float* __restrict__ x,
               const float* __restrict__ w1, const float* __restrict__ b1,
               const float* __restrict__ w2, const float* __restrict__ b2,
               float* __restrict__ y,
               float* __restrict__ gsum, float* __restrict__ gsq, int n) {
    constexpr int K = 64, KP = K + 4;
    extern __shared__ float sm[];
    float* xs   = sm;
    float* ws1T = sm + 128 * KP;
    float* ws2T = ws1T + 64 * KP;
    __shared__ float csum[64], csq[64];

    const int t = threadIdx.x;
    const int lane = t & 31, warp = t >> 5;
    const int g = lane >> 2, tig = lane & 3;
    const int rbase = warp * 16;
    const int node0 = blockIdx.x * 128;

    if (t < 64) { csum[t] = 0.f; csq[t] = 0.f; }
    loadA_mma<K>(xs, x, node0, n, t);
    loadB_mma<K>(ws1T, w1, t);
    loadB_mma<K>(ws2T, w2, t);
    __syncthreads();

    float acc[8][4];
    #pragma unroll
    for (int nt = 0; nt < 8; nt++)
        #pragma unroll
        for (int j = 0; j < 4; j++) acc[nt][j] = 0.f;

    warp_mma<K>(acc, xs, ws1T, rbase, g, tig);
    __syncwarp();
    {
        float* xr0 = xs + (rbase + g) * KP;
        float* xr1 = xs + (rbase + g + 8) * KP;
        #pragma unroll
        for (int nt = 0; nt < 8; nt++) {
            int c = nt * 8 + 2 * tig;
            float2 bb = *(const float2*)(b1 + c);
            xr0[c]     = to_tf32(lrelu(acc[nt][0] + bb.x));
            xr0[c + 1] = to_tf32(lrelu(acc[nt][1] + bb.y));
            xr1[c]     = to_tf32(lrelu(acc[nt][2] + bb.x));
            xr1[c + 1] = to_tf32(lrelu(acc[nt][3] + bb.y));
        }
    }
    __syncwarp();

    #pragma unroll
    for (int nt = 0; nt < 8; nt++)
        #pragma unroll
        for (int j = 0; j < 4; j++) acc[nt][j] = 0.f;

    warp_mma<K>(acc, xs, ws2T, rbase, g, tig);

    int r0 = node0 + rbase + g, r1 = r0 + 8;
    bool v0 = r0 < n, v1 = r1 < n;
    float2 bb0[8], bb1[8];
    #pragma unroll
    for (int nt = 0; nt < 8; nt++) {
        float2 b2v = *(const float2*)(b2 + nt * 8 + 2 * tig);
        bb0[nt] = b2v; bb1[nt] = b2v;
    }
    mma_store_stats(acc, bb0, bb1, r0, r1, v0, v1, tig, lane, y, csum, csq);

    __syncthreads();
    if (t < 64) {
        atomicAdd(&gsum[t], csum[t]);
        atomicAdd(&gsq[t], csq[t]);
    }
}

// ---------------- head GEMM: fused BN1-apply on A-load + code rowbias epilogue ----------------
__global__ void __launch_bounds__(256, 2)
headgemm_kernel(const float* __restrict__ XC, const float* __restrict__ ybuf_in,
                const float* __restrict__ w,
                const float* __restrict__ gsum1, const float* __restrict__ gsq1,
                const float* __restrict__ bn1g, const float* __restrict__ bn1b,
                const float* __restrict__ fc_b1,
                float* __restrict__ y,
                float* __restrict__ gsum, float* __restrict__ gsq, int n) {
    constexpr int K = 128, KP = K + 4;
    extern __shared__ float sm[];
    float* xs  = sm;
    float* wsT = sm + 128 * KP;
    __shared__ float csum[64], csq[64], sc[64], sh[64];

    const int t = threadIdx.x;
    const int lane = t & 31, warp = t >> 5;
    const int g = lane >> 2, tig = lane & 3;
    const int rbase = warp * 16;
    const int node0 = blockIdx.x * 128;

    if (t < 64) {
        csum[t] = 0.f; csq[t] = 0.f;
        float invn = 1.0f / (float)n;
        float m = gsum1[t] * invn;
        float var = gsq1[t] * invn - m * m;
        float s = bn1g[t] * rsqrtf(var + 1e-5f);
        sc[t] = s; sh[t] = bn1b[t] - m * s;
    }
    __syncthreads();

    loadB_mma<K>(wsT, w, t);
    {
        int r = t >> 1;
        int gn = node0 + r;
        if ((t & 1) == 0) {
            const float4* src = (const float4*)(XC + (size_t)gn * 64);
            float* dst = xs + r * KP;
            #pragma unroll
            for (int i = 0; i < 16; i++) {
                float4 v = (gn < n) ? src[i] : make_float4(0.f, 0.f, 0.f, 0.f);
                dst[i * 4 + 0] = to_tf32(v.x); dst[i * 4 + 1] = to_tf32(v.y);
                dst[i * 4 + 2] = to_tf32(v.z); dst[i * 4 + 3] = to_tf32(v.w);
            }
        } else {
            const float4* src = (const float4*)(ybuf_in + (size_t)gn * 64);
            float* dst = xs + r * KP + 64;
            #pragma unroll
            for (int i = 0; i < 16; i++) {
                float4 v = (gn < n) ? src[i] : make_float4(0.f, 0.f, 0.f, 0.f);
                int c = i * 4;
                dst[c + 0] = to_tf32(lrelu(v.x * sc[c + 0] + sh[c + 0]));
                dst[c + 1] = to_tf32(lrelu(v.y * sc[c + 1] + sh[c + 1]));
                dst[c + 2] = to_tf32(lrelu(v.z * sc[c + 2] + sh[c + 2]));
                dst[c + 3] = to_tf32(lrelu(v.w * sc[c + 3] + sh[c + 3]));
            }
        }
    }
    __syncthreads();

    float acc[8][4];
    #pragma unroll
    for (int nt = 0; nt < 8; nt++)
        #pragma unroll
        for (int j = 0; j < 4; j++) acc[nt][j] = 0.f;
    warp_mma<K>(acc, xs, wsT, rbase, g, tig);

    int r0 = node0 + rbase + g, r1 = r0 + 8;
    bool v0 = r0 < n, v1 = r1 < n;
    int code0 = v0 ? d_code[r0] : 0;
    int code1 = v1 ? d_code[r1] : 0;
    const float* fd0 = d_Fdeg + (code0 >> 4) * 64;
    const float* fl0 = d_Flab + (code0 & 15) * 64;
    const float* fd1 = d_Fdeg + (code1 >> 4) * 64;
    const float* fl1 = d_Flab + (code1 & 15) * 64;
    float2 bb0[8], bb1[8];
    #pragma unroll
    for (int nt = 0; nt < 8; nt++) {
        int c = nt * 8 + 2 * tig;
        float2 fb = *(const float2*)(fc_b1 + c);
        float2 a0 = *(const float2*)(fd0 + c);
        float2 l0 = *(const float2*)(fl0 + c);
        float2 a1 = *(const float2*)(fd1 + c);
        float2 l1 = *(const float2*)(fl1 + c);
        bb0[nt] = make_float2(a0.x + l0.x + fb.x, a0.y + l0.y + fb.y);
        bb1[nt] = make_float2(a1.x + l1.x + fb.x, a1.y + l1.y + fb.y);
    }
    mma_store_stats(acc, bb0, bb1, r0, r1, v0, v1, tig, lane, y, csum, csq);

    __syncthreads();
    if (t < 64) {
        atomicAdd(&gsum[t], csum[t]);
        atomicAdd(&gsq[t], csq[t]);
    }
}

// ---------------- BN apply + lrelu (layer 0): writes fp32 XC + fp16 XCh ----------------
__global__ void bnapply_kernel(const float* __restrict__ y,
                               const float* __restrict__ gsum, const float* __restrict__ gsq,
                               const float* __restrict__ g, const float* __restrict__ b,
                               float* __restrict__ out, int n) {
    __shared__ float sc[64], sh[64];
    int t = threadIdx.x;
    if (t < 64) {
        float invn = 1.0f / (float)n;
        float m = gsum[t] * invn;
        float var = gsq[t] * invn - m * m;
        float s = g[t] * rsqrtf(var + 1e-5f);
        sc[t] = s; sh[t] = b[t] - m * s;
    }
    __syncthreads();
    int idx = blockIdx.x * blockDim.x + t;
    int i = idx >> 4, c = idx & 15;
    if (i >= n) return;
    float4 v = ((const float4*)y)[(size_t)i * 16 + c];
    v.x = lrelu(v.x * sc[c * 4 + 0] + sh[c * 4 + 0]);
    v.y = lrelu(v.y * sc[c * 4 + 1] + sh[c * 4 + 1]);
    v.z = lrelu(v.z * sc[c * 4 + 2] + sh[c * 4 + 2]);
    v.w = lrelu(v.w * sc[c * 4 + 3] + sh[c * 4 + 3]);
    ((float4*)out)[(size_t)i * 16 + c] = v;
    uint2 pk;
    __half2 p0 = __floats2half2_rn(v.x, v.y);
    __half2 p1 = __floats2half2_rn(v.z, v.w);
    pk.x = *(const uint32_t*)&p0;
    pk.y = *(const uint32_t*)&p1;
    ((uint2*)d_XCh)[(size_t)i * 16 + c] = pk;
}

// ---------------- head: lrelu(bn(y)) @ fc_w2 + b2 -> sigmoid ----------------
__global__ void head_kernel(const float* __restrict__ y,
                            const float* __restrict__ gsum, const float* __restrict__ gsq,
                            const float* __restrict__ g, const float* __restrict__ b,
                            const float* __restrict__ w2, const float* __restrict__ b2,
                            float* __restrict__ out, int n) {
    __shared__ float sc[64], sh[64];
    int t = threadIdx.x;
    if (t < 64) {
        float invn = 1.0f / (float)n;
        float m = gsum[t] * invn;
        float var = gsq[t] * invn - m * m;
        float s = g[t] * rsqrtf(var + 1e-5f);
        sc[t] = s; sh[t] = b[t] - m * s;
    }
    __syncthreads();
    int lane = t & 31;
    int i = (blockIdx.x * blockDim.x + t) >> 5;
    if (i >= n) return;
    float2 v = ((const float2*)y)[(size_t)i * 32 + lane];
    float z0 = lrelu(v.x * sc[2 * lane] + sh[2 * lane]);
    float z1 = lrelu(v.y * sc[2 * lane + 1] + sh[2 * lane + 1]);
    float a = z0 * w2[2 * lane] + z1 * w2[2 * lane + 1];
    #pragma unroll
    for (int o = 16; o; o >>= 1) a += __shfl_xor_sync(0xffffffffu, a, o);
    if (lane == 0) out[i] = 1.0f / (1.0f + expf(-(a + b2[0])));
}

// ---------------- launch ----------------
extern "C" void kernel_launch(void* const* d_in, const int* in_sizes, int n_in,
                              void* d_out, int out_size) {
    const int*   node_deg = (const int*)d_in[0];
    const int*   node_lab = (const int*)d_in[1];
    const int*   edge     = (const int*)d_in[2];
    const float* emb_deg  = (const float*)d_in[3];
    const float* emb_lab  = (const float*)d_in[4];
    const float* l0_w1 = (const float*)d_in[5];
    const float* l0_b1 = (const float*)d_in[6];
    const float* l0_w2 = (const float*)d_in[7];
    const float* l0_b2 = (const float*)d_in[8];
    const float* l0_eps = (const float*)d_in[9];
    const float* bn0_g = (const float*)d_in[10];
    const float* bn0_b = (const float*)d_in[11];
    const float* l1_w1 = (const float*)d_in[12];
    const float* l1_b1 = (const float*)d_in[13];
    const float* l1_w2 = (const float*)d_in[14];
    const float* l1_b2 = (const float*)d_in[15];
    const float* l1_eps = (const float*)d_in[16];
    const float* bn1_g = (const float*)d_in[17];
    const float* bn1_b = (const float*)d_in[18];
    const float* fc_w1 = (const float*)d_in[19];
    const float* fc_b1 = (const float*)d_in[20];
    const float* fc_bn_g = (const float*)d_in[21];
    const float* fc_bn_b = (const float*)d_in[22];
    const float* fc_w2 = (const float*)d_in[23];
    const float* fc_b2 = (const float*)d_in[24];

    int n = in_sizes[0];
    int E = in_sizes[2] / 2;

    float *XC, *agg, *ybuf, *sumv, *sqv;
    cudaGetSymbolAddress((void**)&XC,   d_XC);
    cudaGetSymbolAddress((void**)&agg,  d_agg);
    cudaGetSymbolAddress((void**)&ybuf, d_ybuf);
    cudaGetSymbolAddress((void**)&sumv, d_sum);
    cudaGetSymbolAddress((void**)&sqv,  d_sq);

    const int SMEM_GIN0    = 25344 * 4;                        // 101376
    const int SMEM_GEMM128 = (128 + 64) * (128 + 4) * 4;       // 101376
    const int SMEM_MLP     = (128 + 64 + 64) * (64 + 4) * 4;   // 69632
    cudaFuncSetAttribute(gin0_kernel,     cudaFuncAttributeMaxDynamicSharedMemorySize, SMEM_GIN0);
    cudaFuncSetAttribute(headgemm_kernel, cudaFuncAttributeMaxDynamicSharedMemorySize, SMEM_GEMM128);
    cudaFuncSetAttribute(mmamlp1_kernel,  cudaFuncAttributeMaxDynamicSharedMemorySize, SMEM_MLP);

    int NB = (n + 1023) / 1024;
    int NZ = (n + 255) / 256;
    int NT = (n + 127) / 128;

    // init (+tables) + CSR build
    zero_tables_kernel<<<NZ + 162, 256>>>(node_deg, node_lab, emb_deg, emb_lab, l0_w1, fc_w1, n, NZ);
    count_kernel<<<(E + 255) / 256, 256>>>(edge, E);
    scanA_kernel<<<NB, 1024>>>(n);
    scanC_kernel<<<NB, 1024>>>(n, NB);
    fill_kernel<<<(E + 255) / 256, 256>>>(edge, E);

    // ---- GIN layer 0: count-GEMM fused kernel ----
    gin0_kernel<<<NT, 256, SMEM_GIN0>>>(l0_eps, l0_b1, l0_w2, l0_b2, ybuf, sumv + 0, sqv + 0, n);
    bnapply_kernel<<<((size_t)n * 16 + 255) / 256, 256>>>(ybuf, sumv + 0, sqv + 0, bn0_g, bn0_b, XC, n);

    // ---- GIN layer 1: fp16 gather + MLP ----
    gather1_kernel<<<((size_t)((n + 1) / 2) * 32 + 255) / 256, 256>>>(l1_eps, n);
    mmamlp1_kernel<<<NT, 256, SMEM_MLP>>>(agg, l1_w1, l1_b1, l1_w2, l1_b2, ybuf, sumv + 64, sqv + 64, n);

    // ---- head: fused BN1-apply + code rowbias ----
    headgemm_kernel<<<NT, 256, SMEM_GEMM128>>>(XC, ybuf, fc_w1 + 128 * 64,
                                               sumv + 64, sqv + 64, bn1_g, bn1_b, fc_b1,
                                               ybuf, sumv + 128, sqv + 128, n);
    head_kernel<<<((size_t)n * 32 + 255) / 256, 256>>>(ybuf, sumv + 128, sqv + 128,
                                                       fc_bn_g, fc_bn_b, fc_w2, fc_b2, (float*)d_out, n);
}

// round 15
// speedup vs baseline: 1.0882x; 1.0058x over previous
#include <cuda_runtime.h>
#include <cuda_bf16.h>
#include <cuda_fp16.h>
#include <math.h>
#include <stdint.h>

// ---------------- problem constants ----------------
#define NMAX 100000
#define EMAX 1200000

// ---------------- device scratch ----------------
__device__ float d_XC[(size_t)NMAX * 64];        // h1 (fp32, for head)
__device__ __half d_XCh[(size_t)NMAX * 64];      // h1 (fp16, for gather1)
__device__ __half d_aggh[(size_t)NMAX * 64];     // layer-1 gather output (fp16)
__device__ float d_ybuf[(size_t)NMAX * 64];      // pre-BN output (reused)
__device__ float d_Tdeg[65 * 128];
__device__ float d_Tlab[16 * 128];
__device__ float d_Fdeg[65 * 64];
__device__ float d_Flab[16 * 64];
__device__ int   d_code[NMAX];
__device__ int   d_cnt[NMAX];
__device__ int   d_cursor[NMAX];
__device__ int   d_rowstart[NMAX + 1];
__device__ int   d_col[EMAX];          // packed: (code << 17) | src_id
__device__ int   d_bsum[128];
__device__ float d_sum[3 * 64];
__device__ float d_sq[3 * 64];

__device__ __forceinline__ float lrelu(float x) { return x > 0.f ? x : 0.01f * x; }

__device__ __forceinline__ float to_tf32(float x) {
    float r;
    asm("cvt.rna.tf32.f32 %0, %1;" : "=f"(r) : "f"(x));
    return r;
}

// mma.sync m16n8k8 tf32: D += A(16x8) * B(8x8), fp32 accumulate
__device__ __forceinline__ void mma_tf32(float (&d)[4], const uint32_t (&a)[4], const uint32_t (&b)[2]) {
    asm volatile("mma.sync.aligned.m16n8k8.row.col.f32.tf32.tf32.f32 "
        "{%0,%1,%2,%3}, {%4,%5,%6,%7}, {%8,%9}, {%0,%1,%2,%3};"
        : "+f"(d[0]), "+f"(d[1]), "+f"(d[2]), "+f"(d[3])
        : "r"(a[0]), "r"(a[1]), "r"(a[2]), "r"(a[3]), "r"(b[0]), "r"(b[1]));
}

// ---------------- init (zero + code pack) and dictionary tables, merged ----------------
__global__ void zero_tables_kernel(const int* __restrict__ deg, const int* __restrict__ lab,
                                   const float* __restrict__ emb_deg,
                                   const float* __restrict__ emb_lab,
                                   const float* __restrict__ l0_w1,
                                   const float* __restrict__ fc_w1,
                                   int n, int nz) {
    __shared__ float e[64];
    int t = threadIdx.x;
    if ((int)blockIdx.x < nz) {
        int i = blockIdx.x * 256 + t;
        if (i < n) {
            d_cnt[i] = 0;
            d_code[i] = (deg[i] << 4) | lab[i];
        }
        if (i < 192) { d_sum[i] = 0.f; d_sq[i] = 0.f; }
        return;
    }
    int b = blockIdx.x - nz;
    const float* erow; const float* w; float* out; int H;
    if (b < 65)       { erow = emb_deg + b * 64;         w = l0_w1;            out = d_Tdeg + b * 128;         H = 128; }
    else if (b < 81)  { erow = emb_lab + (b - 65) * 64;  w = l0_w1 + 64 * 128; out = d_Tlab + (b - 65) * 128;  H = 128; }
    else if (b < 146) { erow = emb_deg + (b - 81) * 64;  w = fc_w1;            out = d_Fdeg + (b - 81) * 64;   H = 64;  }
    else              { erow = emb_lab + (b - 146) * 64; w = fc_w1 + 64 * 64;  out = d_Flab + (b - 146) * 64;  H = 64;  }
    if (t < 64) e[t] = erow[t];
    __syncthreads();
    if (t < H) {
        float s = 0.f;
        #pragma unroll 8
        for (int k = 0; k < 64; k++) s += e[k] * w[k * H + t];
        out[t] = s;
    }
}

// ---------------- CSR build ----------------
__global__ void count_kernel(const int* __restrict__ edge, int e) {
    int i = blockIdx.x * blockDim.x + threadIdx.x;
    if (i < e) atomicAdd(&d_cnt[edge[e + i]], 1);
}

__global__ void scanA_kernel(int n) {
    __shared__ int wsum[32];
    int t = threadIdx.x;
    int idx = blockIdx.x * 1024 + t;
    int v = (idx < n) ? d_cnt[idx] : 0;
    #pragma unroll
    for (int o = 16; o; o >>= 1) v += __shfl_xor_sync(0xffffffffu, v, o);
    if ((t & 31) == 0) wsum[t >> 5] = v;
    __syncthreads();
    if (t < 32) {
        int s = wsum[t];
        #pragma unroll
        for (int o = 16; o; o >>= 1) s += __shfl_xor_sync(0xffffffffu, s, o);
        if (t == 0) d_bsum[blockIdx.x] = s;
    }
}

// scanC with integrated block-offset scan; also initializes cursor = rowstart
__global__ void scanC_kernel(int n, int nb) {
    __shared__ int wsum[32];
    __shared__ int sb[128];
    int t = threadIdx.x;
    if (t < 128) sb[t] = (t < nb) ? d_bsum[t] : 0;
    __syncthreads();
    #pragma unroll
    for (int o = 1; o < 128; o <<= 1) {
        int u = (t < 128 && t >= o) ? sb[t - o] : 0;
        __syncthreads();
        if (t < 128) sb[t] += u;
        __syncthreads();
    }
    int boff = (blockIdx.x == 0) ? 0 : sb[blockIdx.x - 1];
    if (blockIdx.x == 0 && t == 0) d_rowstart[n] = sb[nb - 1];

    int idx = blockIdx.x * 1024 + t;
    int v = (idx < n) ? d_cnt[idx] : 0;
    int lane = t & 31, wid = t >> 5;
    int inc = v;
    #pragma unroll
    for (int o = 1; o < 32; o <<= 1) {
        int u = __shfl_up_sync(0xffffffffu, inc, o);
        if (lane >= o) inc += u;
    }
    if (lane == 31) wsum[wid] = inc;
    __syncthreads();
    if (t < 32) {
        int s = wsum[t];
        int sInc = s;
        #pragma unroll
        for (int o = 1; o < 32; o <<= 1) {
            int u = __shfl_up_sync(0xffffffffu, sInc, o);
            if (t >= o) sInc += u;
        }
        wsum[t] = sInc - s;
    }
    __syncthreads();
    if (idx < n) {
        int rs = boff + wsum[wid] + inc - v;
        d_rowstart[idx] = rs;
        d_cursor[idx] = rs;
    }
}

// fill: pack neighbor code into high bits (id < 2^17, code 11 bits)
__global__ void fill_kernel(const int* __restrict__ edge, int e) {
    int i = blockIdx.x * blockDim.x + threadIdx.x;
    if (i < e) {
        int s = edge[i];
        int d = edge[e + i];
        int p = atomicAdd(&d_cursor[d], 1);
        d_col[p] = (d_code[s] << 17) | s;
    }
}

// ---------------- fused GIN layer 0 as count-GEMM ----------------
__global__ void __launch_bounds__(256, 2)
gin0_kernel(const float* __restrict__ epsp, const float* __restrict__ b1,
            const float* __restrict__ w2, const float* __restrict__ b2,
            float* __restrict__ y,
            float* __restrict__ gsum, float* __restrict__ gsq, int n) {
    constexpr int KP1 = 92;    // 88 + 4 pad
    constexpr int KP2 = 132;   // 128 + 4 pad
    extern __shared__ float sm[];
    float* Cm = sm;                    // stage1 A: counts [128][92]
    float* Ts = sm + 13568;            // stage1 B: table [128 cols][92]
    float* hid = sm;                   // stage2 A: hidden [128][132]
    float* w2T = sm + 16896;           // stage2 B: [64][132]
    __shared__ float csum[64], csq[64];

    const int t = threadIdx.x;
    const int lane = t & 31, warp = t >> 5;
    const int g = lane >> 2, tig = lane & 3;
    const int rbase = warp * 16;
    const int node0 = blockIdx.x * 128;

    if (t < 64) { csum[t] = 0.f; csq[t] = 0.f; }
    for (int idx = t; idx < 128 * KP1; idx += 256) Cm[idx] = 0.f;
    for (int idx = t; idx < 128 * KP1; idx += 256) {
        int c = idx / KP1, k = idx - c * KP1;
        float v = 0.f;
        if (k < 65) v = d_Tdeg[k * 128 + c];
        else if (k < 81) v = d_Tlab[(k - 65) * 128 + c];
        Ts[idx] = to_tf32(v);
    }
    __syncthreads();

    // build counts: 2 threads per row, smem atomics
    {
        float e1 = 1.0f + epsp[0];
        int r = t >> 1, part = t & 1;
        int i = node0 + r;
        float* Crow = Cm + r * KP1;
        if (i < n) {
            if (part == 0) {
                int self = d_code[i];
                atomicAdd(&Crow[self >> 4], e1);
                atomicAdd(&Crow[65 + (self & 15)], e1);
            }
            int js = d_rowstart[i], je = d_rowstart[i + 1];
            for (int j = js + part; j < je; j += 2) {
                int cd = d_col[j] >> 17;
                atomicAdd(&Crow[cd >> 4], 1.0f);
                atomicAdd(&Crow[65 + (cd & 15)], 1.0f);
            }
        }
    }
    __syncthreads();

    // stage 1: agg(128 cols) = C @ T ; K=88
    float acc1[16][4];
    #pragma unroll
    for (int nt = 0; nt < 16; nt++)
        #pragma unroll
        for (int j = 0; j < 4; j++) acc1[nt][j] = 0.f;
    {
        const float* xr0 = Cm + (rbase + g) * KP1;
        const float* xr1 = Cm + (rbase + g + 8) * KP1;
        #pragma unroll
        for (int ks = 0; ks < 11; ks++) {
            int k0 = ks * 8;
            uint32_t a[4];
            a[0] = __float_as_uint(xr0[k0 + tig]);
            a[1] = __float_as_uint(xr1[k0 + tig]);
            a[2] = __float_as_uint(xr0[k0 + tig + 4]);
            a[3] = __float_as_uint(xr1[k0 + tig + 4]);
            #pragma unroll
            for (int nt = 0; nt < 16; nt++) {
                const float* wr = Ts + (nt * 8 + g) * KP1;
                uint32_t b[2];
                b[0] = __float_as_uint(wr[k0 + tig]);
                b[1] = __float_as_uint(wr[k0 + 4 + tig]);
                mma_tf32(acc1[nt], a, b);
            }
        }
    }
    __syncthreads();

    // hidden = tf32(lrelu(agg + b1)) -> hid; concurrently load w2T
    {
        float* h0 = hid + (rbase + g) * KP2;
        float* h1 = hid + (rbase + g + 8) * KP2;
        #pragma unroll
        for (int nt = 0; nt < 16; nt++) {
            int c = nt * 8 + 2 * tig;
            float2 bb = *(const float2*)(b1 + c);
            h0[c]     = to_tf32(lrelu(acc1[nt][0] + bb.x));
            h0[c + 1] = to_tf32(lrelu(acc1[nt][1] + bb.y));
            h1[c]     = to_tf32(lrelu(acc1[nt][2] + bb.x));
            h1[c + 1] = to_tf32(lrelu(acc1[nt][3] + bb.y));
        }
    }
    #pragma unroll
    for (int i = 0; i < 32; i++) {
        int idx = t + i * 256;
        int k = idx >> 6, nn = idx & 63;
        w2T[nn * KP2 + k] = to_tf32(w2[idx]);
    }
    __syncthreads();

    // stage 2: y = hidden @ w2 + b2
    float acc[8][4];
    #pragma unroll
    for (int nt = 0; nt < 8; nt++)
        #pragma unroll
        for (int j = 0; j < 4; j++) acc[nt][j] = 0.f;
    {
        const float* xr0 = hid + (rbase + g) * KP2;
        const float* xr1 = hid + (rbase + g + 8) * KP2;
        #pragma unroll
        for (int ks = 0; ks < 16; ks++) {
            int k0 = ks * 8;
            uint32_t a[4];
            a[0] = __float_as_uint(xr0[k0 + tig]);
            a[1] = __float_as_uint(xr1[k0 + tig]);
            a[2] = __float_as_uint(xr0[k0 + tig + 4]);
            a[3] = __float_as_uint(xr1[k0 + tig + 4]);
            #pragma unroll
            for (int nt = 0; nt < 8; nt++) {
                const float* wr = w2T + (nt * 8 + g) * KP2;
                uint32_t b[2];
                b[0] = __float_as_uint(wr[k0 + tig]);
                b[1] = __float_as_uint(wr[k0 + 4 + tig]);
                mma_tf32(acc[nt], a, b);
            }
        }
    }

    int r0 = node0 + rbase + g, r1 = r0 + 8;
    bool v0 = r0 < n, v1 = r1 < n;
    float ps[8][2], pq[8][2];
    #pragma unroll
    for (int nt = 0; nt < 8; nt++) {
        int c = nt * 8 + 2 * tig;
        float2 bb = *(const float2*)(b2 + c);
        float v00 = acc[nt][0] + bb.x, v01 = acc[nt][1] + bb.y;
        float v10 = acc[nt][2] + bb.x, v11 = acc[nt][3] + bb.y;
        float s0 = 0.f, s1 = 0.f, q0 = 0.f, q1 = 0.f;
        if (v0) { s0 += v00; s1 += v01; q0 += v00 * v00; q1 += v01 * v01; }
        if (v1) { s0 += v10; s1 += v11; q0 += v10 * v10; q1 += v11 * v11; }
        ps[nt][0] = s0; ps[nt][1] = s1; pq[nt][0] = q0; pq[nt][1] = q1;
        if (v0) *(float2*)(y + (size_t)r0 * 64 + c) = make_float2(v00, v01);
        if (v1) *(float2*)(y + (size_t)r1 * 64 + c) = make_float2(v10, v11);
    }
    #pragma unroll
    for (int o = 4; o <= 16; o <<= 1) {
        #pragma unroll
        for (int nt = 0; nt < 8; nt++) {
            ps[nt][0] += __shfl_xor_sync(0xffffffffu, ps[nt][0], o);
            ps[nt][1] += __shfl_xor_sync(0xffffffffu, ps[nt][1], o);
            pq[nt][0] += __shfl_xor_sync(0xffffffffu, pq[nt][0], o);
            pq[nt][1] += __shfl_xor_sync(0xffffffffu, pq[nt][1], o);
        }
    }
    if (lane < 4) {
        #pragma unroll
        for (int nt = 0; nt < 8; nt++) {
            int c = nt * 8 + 2 * tig;
            atomicAdd(&csum[c], ps[nt][0]);
            atomicAdd(&csum[c + 1], ps[nt][1]);
            atomicAdd(&csq[c], pq[nt][0]);
            atomicAdd(&csq[c + 1], pq[nt][1]);
        }
    }
    __syncthreads();
    if (t < 64) {
        atomicAdd(&gsum[t], csum[t]);
        atomicAdd(&gsq[t], csq[t]);
    }
}

// ---------------- layer-1 aggregation (fp16 source, fp32 accumulate, fp16 out) ----------------
__global__ void gather1_kernel(const float* __restrict__ epsp, int n) {
    int lane = threadIdx.x & 31;
    int warp = (blockIdx.x * blockDim.x + threadIdx.x) >> 5;
    int i = warp * 2 + (lane >> 4);
    int c = lane & 15;
    if (i >= n) return;
    float e1 = 1.0f + epsp[0];
    const uint2* hb2 = (const uint2*)d_XCh;
    uint2 raw = hb2[(size_t)i * 16 + c];
    float2 a01 = __half22float2(*(const __half2*)&raw.x);
    float2 a23 = __half22float2(*(const __half2*)&raw.y);
    float4 s = make_float4(a01.x * e1, a01.y * e1, a23.x * e1, a23.y * e1);
    int js = d_rowstart[i], je = d_rowstart[i + 1];
    for (int j = js; j < je; j++) {
        int nb = d_col[j] & 0x1FFFF;
        uint2 r = hb2[(size_t)nb * 16 + c];
        float2 v01 = __half22float2(*(const __half2*)&r.x);
        float2 v23 = __half22float2(*(const __half2*)&r.y);
        s.x += v01.x; s.y += v01.y; s.z += v23.x; s.w += v23.y;
    }
    uint2 pk;
    __half2 p0 = __floats2half2_rn(s.x, s.y);
    __half2 p1 = __floats2half2_rn(s.z, s.w);
    pk.x = *(const uint32_t*)&p0;
    pk.y = *(const uint32_t*)&p1;
    ((uint2*)d_aggh)[(size_t)i * 16 + c] = pk;
}

// ================= warp-level tf32 MMA GEMM building blocks =================
template <int K>
__device__ __forceinline__ void loadB_mma(float* wsT, const float* __restrict__ w, int t) {
    constexpr int KP = K + 4;
    #pragma unroll
    for (int i = 0; i < K * 64 / 256; i++) {
        int idx = t + i * 256;
        int k = idx >> 6, nn = idx & 63;
        wsT[nn * KP + k] = to_tf32(w[idx]);
    }
}

template <int K>
__device__ __forceinline__ void warp_mma(float (&acc)[8][4], const float* xs, const float* wsT,
                                         int rbase, int g, int tig) {
    constexpr int KP = K + 4;
    const float* xr0 = xs + (rbase + g) * KP;
    const float* xr1 = xs + (rbase + g + 8) * KP;
    #pragma unroll
    for (int ks = 0; ks < K / 8; ks++) {
        int k0 = ks * 8;
        uint32_t a[4];
        a[0] = __float_as_uint(xr0[k0 + tig]);
        a[1] = __float_as_uint(xr1[k0 + tig]);
        a[2] = __float_as_uint(xr0[k0 + tig + 4]);
        a[3] = __float_as_uint(xr1[k0 + tig + 4]);
        #pragma unroll
        for (int nt = 0; nt < 8; nt++) {
            const float* wr = wsT + (nt * 8 + g) * KP;
            uint32_t b[2];
            b[0] = __float_as_uint(wr[k0 + tig]);
            b[1] = __float_as_uint(wr[k0 + 4 + tig]);
            mma_tf32(acc[nt], a, b);
        }
    }
}

// stats + store epilogue
__device__ __forceinline__ void mma_store_stats(float (&acc)[8][4],
                                                const float2 (&bb0)[8], const float2 (&bb1)[8],
                                                int r0, int r1, bool v0, bool v1, int tig, int lane,
                                                float* __restrict__ y, float* csum, float* csq) {
    float ps[8][2], pq[8][2];
    #pragma unroll
    for (int nt = 0; nt < 8; nt++) {
        int c = nt * 8 + 2 * tig;
        float v00 = acc[nt][0] + bb0[nt].x, v01 = acc[nt][1] + bb0[nt].y;
        float v10 = acc[nt][2] + bb1[nt].x, v11 = acc[nt][3] + bb1[nt].y;
        float s0 = 0.f, s1 = 0.f, q0 = 0.f, q1 = 0.f;
        if (v0) { s0 += v00; s1 += v01; q0 += v00 * v00; q1 += v01 * v01; }
        if (v1) { s0 += v10; s1 += v11; q0 += v10 * v10; q1 += v11 * v11; }
        ps[nt][0] = s0; ps[nt][1] = s1; pq[nt][0] = q0; pq[nt][1] = q1;
        if (v0) *(float2*)(y + (size_t)r0 * 64 + c) = make_float2(v00, v01);
        if (v1) *(float2*)(y + (size_t)r1 * 64 + c) = make_float2(v10, v11);
    }
    #pragma unroll
    for (int o = 4; o <= 16; o <<= 1) {
        #pragma unroll
        for (int nt = 0; nt < 8; nt++) {
            ps[nt][0] += __shfl_xor_sync(0xffffffffu, ps[nt][0], o);
            ps[nt][1] += __shfl_xor_sync(0xffffffffu, ps[nt][1], o);
            pq[nt][0] += __shfl_xor_sync(0xffffffffu, pq[nt][0], o);
            pq[nt][1] += __shfl_xor_sync(0xffffffffu, pq[nt][1], o);
        }
    }
    if (lane < 4) {
        #pragma unroll
        for (int nt = 0; nt < 8; nt++) {
            int c = nt * 8 + 2 * tig;
            atomicAdd(&csum[c], ps[nt][0]);
            atomicAdd(&csum[c + 1], ps[nt][1]);
            atomicAdd(&csq[c], pq[nt][0]);
            atomicAdd(&csq[c + 1], pq[nt][1]);
        }
    }
}

// ---------------- layer-1 MLP (tf32 MMA, fp16 A source): y = lrelu(x@w1+b1)@w2+b2 ----------------
__global__ void __launch_bounds__(256, 2)
mmamlp1_kernel(const float* __restrict__ w1, const float* __restrict__ b1,
               const float* __restrict__ w2, const float* __restrict__ b2,
               float* __restrict__ y,
               float* __restrict__ gsum, float* __restrict__ gsq, int n) {
    constexpr int K = 64, KP = K + 4;
    extern __shared__ float sm[];
    float* xs   = sm;
    float* ws1T = sm + 128 * KP;
    float* ws2T = ws1T + 64 * KP;
    __shared__ float csum[64], csq[64];

    const int t = threadIdx.x;
    const int lane = t & 31, warp = t >> 5;
    const int g = lane >> 2, tig = lane & 3;
    const int rbase = warp * 16;
    const int node0 = blockIdx.x * 128;

    if (t < 64) { csum[t] = 0.f; csq[t] = 0.f; }
    // A load from fp16 aggh: thread t loads row t>>1, 32 halves at (t&1)*32
    {
        int r = t >> 1;
        int cb = (t & 1) * 32;
        int gn = node0 + r;
        const uint4* src = (const uint4*)(d_aggh + (size_t)gn * 64 + cb);
        float* dst = xs + r * KP + cb;
        #pragma unroll
        for (int i = 0; i < 4; i++) {
            uint4 v = (gn < n) ? src[i] : make_uint4(0u, 0u, 0u, 0u);
            float2 f0 = __half22float2(*(const __half2*)&v.x);
            float2 f1 = __half22float2(*(const __half2*)&v.y);
            float2 f2 = __half22float2(*(const __half2*)&v.z);
            float2 f3 = __half22float2(*(const __half2*)&v.w);
            dst[i * 8 + 0] = to_tf32(f0.x); dst[i * 8 + 1] = to_tf32(f0.y);
            dst[i * 8 + 2] = to_tf32(f1.x); dst[i * 8 + 3] = to_tf32(f1.y);
            dst[i * 8 + 4] = to_tf32(f2.x); dst[i * 8 + 5] = to_tf32(f2.y);
            dst[i * 8 + 6] = to_tf32(f3.x); dst[i * 8 + 7] = to_tf32(f3.y);
        }
    }
    loadB_mma<K>(ws1T, w1, t);
    loadB_mma<K>(ws2T, w2, t);
    __syncthreads();

    float acc[8][4];
    #pragma unroll
    for (int nt = 0; nt < 8; nt++)
        #pragma unroll
        for (int j = 0; j < 4; j++) acc[nt][j] = 0.f;

    warp_mma<K>(acc, xs, ws1T, rbase, g, tig);
    __syncwarp();
    {
        float* xr0 = xs + (rbase + g) * KP;
        float* xr1 = xs + (rbase + g + 8) * KP;
        #pragma unroll
        for (int nt = 0; nt < 8; nt++) {
            int c = nt * 8 + 2 * tig;
            float2 bb = *(const float2*)(b1 + c);
            xr0[c]     = to_tf32(lrelu(acc[nt][0] + bb.x));
            xr0[c + 1] = to_tf32(lrelu(acc[nt][1] + bb.y));
            xr1[c]     = to_tf32(lrelu(acc[nt][2] + bb.x));
            xr1[c + 1] = to_tf32(lrelu(acc[nt][3] + bb.y));
        }
    }
    __syncwarp();

    #pragma unroll
    for (int nt = 0; nt < 8; nt++)
        #pragma unroll
        for (int j = 0; j < 4; j++) acc[nt][j] = 0.f;

    warp_mma<K>(acc, xs, ws2T, rbase, g, tig);

    int r0 = node0 + rbase + g, r1 = r0 + 8;
    bool v0 = r0 < n, v1 = r1 < n;
    float2 bb0[8], bb1[8];
    #pragma unroll
    for (int nt = 0; nt < 8; nt++) {
        float2 b2v = *(const float2*)(b2 + nt * 8 + 2 * tig);
        bb0[nt] = b2v; bb1[nt] = b2v;
    }
    mma_store_stats(acc, bb0, bb1, r0, r1, v0, v1, tig, lane, y, csum, csq);

    __syncthreads();
    if (t < 64) {
        atomicAdd(&gsum[t], csum[t]);
        atomicAdd(&gsq[t], csq[t]);
    }
}

// ---------------- head GEMM: fused BN1-apply on A-load + code rowbias epilogue ----------------
__global__ void __launch_bounds__(256, 2)
headgemm_kernel(const float* __restrict__ XC, const float* __restrict__ ybuf_in,
                const float* __restrict__ w,
                const float* __restrict__ gsum1, const float* __restrict__ gsq1,
                const float* __restrict__ bn1g, const float* __restrict__ bn1b,
                const float* __restrict__ fc_b1,
                float* __restrict__ y,
                float* __restrict__ gsum, float* __restrict__ gsq, int n) {
    constexpr int K = 128, KP = K + 4;
    extern __shared__ float sm[];
    float* xs  = sm;
    float* wsT = sm + 128 * KP;
    __shared__ float csum[64], csq[64], sc[64], sh[64];

    const int t = threadIdx.x;
    const int lane = t & 31, warp = t >> 5;
    const int g = lane >> 2, tig = lane & 3;
    const int rbase = warp * 16;
    const int node0 = blockIdx.x * 128;

    if (t < 64) {
        csum[t] = 0.f; csq[t] = 0.f;
        float invn = 1.0f / (float)n;
        float m = gsum1[t] * invn;
        float var = gsq1[t] * invn - m * m;
        float s = bn1g[t] * rsqrtf(var + 1e-5f);
        sc[t] = s; sh[t] = bn1b[t] - m * s;
    }
    __syncthreads();

    loadB_mma<K>(wsT, w, t);
    {
        int r = t >> 1;
        int gn = node0 + r;
        if ((t & 1) == 0) {
            const float4* src = (const float4*)(XC + (size_t)gn * 64);
            float* dst = xs + r * KP;
            #pragma unroll
            for (int i = 0; i < 16; i++) {
                float4 v = (gn < n) ? src[i] : make_float4(0.f, 0.f, 0.f, 0.f);
                dst[i * 4 + 0] = to_tf32(v.x); dst[i * 4 + 1] = to_tf32(v.y);
                dst[i * 4 + 2] = to_tf32(v.z); dst[i * 4 + 3] = to_tf32(v.w);
            }
        } else {
            const float4* src = (const float4*)(ybuf_in + (size_t)gn * 64);
            float* dst = xs + r * KP + 64;
            #pragma unroll
            for (int i = 0; i < 16; i++) {
                float4 v = (gn < n) ? src[i] : make_float4(0.f, 0.f, 0.f, 0.f);
                int c = i * 4;
                dst[c + 0] = to_tf32(lrelu(v.x * sc[c + 0] + sh[c + 0]));
                dst[c + 1] = to_tf32(lrelu(v.y * sc[c + 1] + sh[c + 1]));
                dst[c + 2] = to_tf32(lrelu(v.z * sc[c + 2] + sh[c + 2]));
                dst[c + 3] = to_tf32(lrelu(v.w * sc[c + 3] + sh[c + 3]));
            }
        }
    }
    __syncthreads();

    float acc[8][4];
    #pragma unroll
    for (int nt = 0; nt < 8; nt++)
        #pragma unroll
        for (int j = 0; j < 4; j++) acc[nt][j] = 0.f;
    warp_mma<K>(acc, xs, wsT, rbase, g, tig);

    int r0 = node0 + rbase + g, r1 = r0 + 8;
    bool v0 = r0 < n, v1 = r1 < n;
    int code0 = v0 ? d_code[r0] : 0;
    int code1 = v1 ? d_code[r1] : 0;
    const float* fd0 = d_Fdeg + (code0 >> 4) * 64;
    const float* fl0 = d_Flab + (code0 & 15) * 64;
    const float* fd1 = d_Fdeg + (code1 >> 4) * 64;
    const float* fl1 = d_Flab + (code1 & 15) * 64;
    float2 bb0[8], bb1[8];
    #pragma unroll
    for (int nt = 0; nt < 8; nt++) {
        int c = nt * 8 + 2 * tig;
        float2 fb = *(const float2*)(fc_b1 + c);
        float2 a0 = *(const float2*)(fd0 + c);
        float2 l0 = *(const float2*)(fl0 + c);
        float2 a1 = *(const float2*)(fd1 + c);
        float2 l1 = *(const float2*)(fl1 + c);
        bb0[nt] = make_float2(a0.x + l0.x + fb.x, a0.y + l0.y + fb.y);
        bb1[nt] = make_float2(a1.x + l1.x + fb.x, a1.y + l1.y + fb.y);
    }
    mma_store_stats(acc, bb0, bb1, r0, r1, v0, v1, tig, lane, y, csum, csq);

    __syncthreads();
    if (t < 64) {
        atomicAdd(&gsum[t], csum[t]);
        atomicAdd(&gsq[t], csq[t]);
    }
}

// ---------------- BN apply + lrelu (layer 0): writes fp32 XC + fp16 XCh ----------------
__global__ void bnapply_kernel(const float* __restrict__ y,
                               const float* __restrict__ gsum, const float* __restrict__ gsq,
                               const float* __restrict__ g, const float* __restrict__ b,
                               float* __restrict__ out, int n) {
    __shared__ float sc[64], sh[64];
    int t = threadIdx.x;
    if (t < 64) {
        float invn = 1.0f / (float)n;
        float m = gsum[t] * invn;
        float var = gsq[t] * invn - m * m;
        float s = g[t] * rsqrtf(var + 1e-5f);
        sc[t] = s; sh[t] = b[t] - m * s;
    }
    __syncthreads();
    int idx = blockIdx.x * blockDim.x + t;
    int i = idx >> 4, c = idx & 15;
    if (i >= n) return;
    float4 v = ((const float4*)y)[(size_t)i * 16 + c];
    v.x = lrelu(v.x * sc[c * 4 + 0] + sh[c * 4 + 0]);
    v.y = lrelu(v.y * sc[c * 4 + 1] + sh[c * 4 + 1]);
    v.z = lrelu(v.z * sc[c * 4 + 2] + sh[c * 4 + 2]);
    v.w = lrelu(v.w * sc[c * 4 + 3] + sh[c * 4 + 3]);
    ((float4*)out)[(size_t)i * 16 + c] = v;
    uint2 pk;
    __half2 p0 = __floats2half2_rn(v.x, v.y);
    __half2 p1 = __floats2half2_rn(v.z, v.w);
    pk.x = *(const uint32_t*)&p0;
    pk.y = *(const uint32_t*)&p1;
    ((uint2*)d_XCh)[(size_t)i * 16 + c] = pk;
}

// ---------------- head: lrelu(bn(y)) @ fc_w2 + b2 -> sigmoid ----------------
__global__ void head_kernel(const float* __restrict__ y,
                            const float* __restrict__ gsum, const float* __restrict__ gsq,
                            const float* __restrict__ g, const float* __restrict__ b,
                            const float* __restrict__ w2, const float* __restrict__ b2,
                            float* __restrict__ out, int n) {
    __shared__ float sc[64], sh[64];
    int t = threadIdx.x;
    if (t < 64) {
        float invn = 1.0f / (float)n;
        float m = gsum[t] * invn;
        float var = gsq[t] * invn - m * m;
        float s = g[t] * rsqrtf(var + 1e-5f);
        sc[t] = s; sh[t] = b[t] - m * s;
    }
    __syncthreads();
    int lane = t & 31;
    int i = (blockIdx.x * blockDim.x + t) >> 5;
    if (i >= n) return;
    float2 v = ((const float2*)y)[(size_t)i * 32 + lane];
    float z0 = lrelu(v.x * sc[2 * lane] + sh[2 * lane]);
    float z1 = lrelu(v.y * sc[2 * lane + 1] + sh[2 * lane + 1]);
    float a = z0 * w2[2 * lane] + z1 * w2[2 * lane + 1];
    #pragma unroll
    for (int o = 16; o; o >>= 1) a += __shfl_xor_sync(0xffffffffu, a, o);
    if (lane == 0) out[i] = 1.0f / (1.0f + expf(-(a + b2[0])));
}

// ---------------- launch ----------------
extern "C" void kernel_launch(void* const* d_in, const int* in_sizes, int n_in,
                              void* d_out, int out_size) {
    const int*   node_deg = (const int*)d_in[0];
    const int*   node_lab = (const int*)d_in[1];
    const int*   edge     = (const int*)d_in[2];
    const float* emb_deg  = (const float*)d_in[3];
    const float* emb_lab  = (const float*)d_in[4];
    const float* l0_w1 = (const float*)d_in[5];
    const float* l0_b1 = (const float*)d_in[6];
    const float* l0_w2 = (const float*)d_in[7];
    const float* l0_b2 = (const float*)d_in[8];
    const float* l0_eps = (const float*)d_in[9];
    const float* bn0_g = (const float*)d_in[10];
    const float* bn0_b = (const float*)d_in[11];
    const float* l1_w1 = (const float*)d_in[12];
    const float* l1_b1 = (const float*)d_in[13];
    const float* l1_w2 = (const float*)d_in[14];
    const float* l1_b2 = (const float*)d_in[15];
    const float* l1_eps = (const float*)d_in[16];
    const float* bn1_g = (const float*)d_in[17];
    const float* bn1_b = (const float*)d_in[18];
    const float* fc_w1 = (const float*)d_in[19];
    const float* fc_b1 = (const float*)d_in[20];
    const float* fc_bn_g = (const float*)d_in[21];
    const float* fc_bn_b = (const float*)d_in[22];
    const float* fc_w2 = (const float*)d_in[23];
    const float* fc_b2 = (const float*)d_in[24];

    int n = in_sizes[0];
    int E = in_sizes[2] / 2;

    float *XC, *ybuf, *sumv, *sqv;
    cudaGetSymbolAddress((void**)&XC,   d_XC);
    cudaGetSymbolAddress((void**)&ybuf, d_ybuf);
    cudaGetSymbolAddress((void**)&sumv, d_sum);
    cudaGetSymbolAddress((void**)&sqv,  d_sq);

    const int SMEM_GIN0    = 25344 * 4;                        // 101376
    const int SMEM_GEMM128 = (128 + 64) * (128 + 4) * 4;       // 101376
    const int SMEM_MLP     = (128 + 64 + 64) * (64 + 4) * 4;   // 69632
    cudaFuncSetAttribute(gin0_kernel,     cudaFuncAttributeMaxDynamicSharedMemorySize, SMEM_GIN0);
    cudaFuncSetAttribute(headgemm_kernel, cudaFuncAttributeMaxDynamicSharedMemorySize, SMEM_GEMM128);
    cudaFuncSetAttribute(mmamlp1_kernel,  cudaFuncAttributeMaxDynamicSharedMemorySize, SMEM_MLP);

    int NB = (n + 1023) / 1024;
    int NZ = (n + 255) / 256;
    int NT = (n + 127) / 128;

    // init (+tables) + CSR build
    zero_tables_kernel<<<NZ + 162, 256>>>(node_deg, node_lab, emb_deg, emb_lab, l0_w1, fc_w1, n, NZ);
    count_kernel<<<(E + 255) / 256, 256>>>(edge, E);
    scanA_kernel<<<NB, 1024>>>(n);
    scanC_kernel<<<NB, 1024>>>(n, NB);
    fill_kernel<<<(E + 255) / 256, 256>>>(edge, E);

    // ---- GIN layer 0: count-GEMM fused kernel ----
    gin0_kernel<<<NT, 256, SMEM_GIN0>>>(l0_eps, l0_b1, l0_w2, l0_b2, ybuf, sumv + 0, sqv + 0, n);
    bnapply_kernel<<<((size_t)n * 16 + 255) / 256, 256>>>(ybuf, sumv + 0, sqv + 0, bn0_g, bn0_b, XC, n);

    // ---- GIN layer 1: fp16 gather -> fp16 agg -> MLP ----
    gather1_kernel<<<((size_t)((n + 1) / 2) * 32 + 255) / 256, 256>>>(l1_eps, n);
    mmamlp1_kernel<<<NT, 256, SMEM_MLP>>>(l1_w1, l1_b1, l1_w2, l1_b2, ybuf, sumv + 64, sqv + 64, n);

    // ---- head: fused BN1-apply + code rowbias ----
    headgemm_kernel<<<NT, 256, SMEM_GEMM128>>>(XC, ybuf, fc_w1 + 128 * 64,
                                               sumv + 64, sqv + 64, bn1_g, bn1_b, fc_b1,
                                               ybuf, sumv + 128, sqv + 128, n);
    head_kernel<<<((size_t)n * 32 + 255) / 256, 256>>>(ybuf, sumv + 128, sqv + 128,
                                                       fc_bn_g, fc_bn_b, fc_w2, fc_b2, (float*)d_out, n);
}

// round 16
// speedup vs baseline: 1.1589x; 1.0650x over previous
#include <cuda_runtime.h>
#include <cuda_bf16.h>
#include <cuda_fp16.h>
#include <math.h>
#include <stdint.h>

// ---------------- problem constants ----------------
#define NMAX 100000
#define EMAX 1200000

// ---------------- device scratch ----------------
__device__ __half d_XCh[(size_t)NMAX * 64];      // h1 (fp16: for gather1 + head)
__device__ __half d_aggh[(size_t)NMAX * 64];     // layer-1 gather output (fp16)
__device__ float d_ybuf[(size_t)NMAX * 64];      // pre-BN output (reused)
__device__ float d_Tdeg[65 * 128];
__device__ float d_Tlab[16 * 128];
__device__ float d_Fdeg[65 * 64];
__device__ float d_Flab[16 * 64];
__device__ int   d_code[NMAX];
__device__ int   d_cnt[NMAX];
__device__ int   d_cursor[NMAX];
__device__ int   d_rowstart[NMAX + 1];
__device__ int   d_col[EMAX];          // packed: (code << 17) | src_id
__device__ int   d_bsum[128];
__device__ int   d_done;
__device__ float d_sum[3 * 64];
__device__ float d_sq[3 * 64];

__device__ __forceinline__ float lrelu(float x) { return x > 0.f ? x : 0.01f * x; }

__device__ __forceinline__ float to_tf32(float x) {
    float r;
    asm("cvt.rna.tf32.f32 %0, %1;" : "=f"(r) : "f"(x));
    return r;
}

// mma.sync m16n8k8 tf32: D += A(16x8) * B(8x8), fp32 accumulate
__device__ __forceinline__ void mma_tf32(float (&d)[4], const uint32_t (&a)[4], const uint32_t (&b)[2]) {
    asm volatile("mma.sync.aligned.m16n8k8.row.col.f32.tf32.tf32.f32 "
        "{%0,%1,%2,%3}, {%4,%5,%6,%7}, {%8,%9}, {%0,%1,%2,%3};"
        : "+f"(d[0]), "+f"(d[1]), "+f"(d[2]), "+f"(d[3])
        : "r"(a[0]), "r"(a[1]), "r"(a[2]), "r"(a[3]), "r"(b[0]), "r"(b[1]));
}

// ---------------- init (zero + code pack) and dictionary tables, merged ----------------
__global__ void zero_tables_kernel(const int* __restrict__ deg, const int* __restrict__ lab,
                                   const float* __restrict__ emb_deg,
                                   const float* __restrict__ emb_lab,
                                   const float* __restrict__ l0_w1,
                                   const float* __restrict__ fc_w1,
                                   int n, int nz) {
    __shared__ float e[64];
    int t = threadIdx.x;
    if ((int)blockIdx.x < nz) {
        int i = blockIdx.x * 256 + t;
        if (i < n) {
            d_cnt[i] = 0;
            d_code[i] = (deg[i] << 4) | lab[i];
        }
        if (i < 192) { d_sum[i] = 0.f; d_sq[i] = 0.f; }
        if (blockIdx.x == 0 && t == 0) d_done = 0;
        return;
    }
    int b = blockIdx.x - nz;
    const float* erow; const float* w; float* out; int H;
    if (b < 65)       { erow = emb_deg + b * 64;         w = l0_w1;            out = d_Tdeg + b * 128;         H = 128; }
    else if (b < 81)  { erow = emb_lab + (b - 65) * 64;  w = l0_w1 + 64 * 128; out = d_Tlab + (b - 65) * 128;  H = 128; }
    else if (b < 146) { erow = emb_deg + (b - 81) * 64;  w = fc_w1;            out = d_Fdeg + (b - 81) * 64;   H = 64;  }
    else              { erow = emb_lab + (b - 146) * 64; w = fc_w1 + 64 * 64;  out = d_Flab + (b - 146) * 64;  H = 64;  }
    if (t < 64) e[t] = erow[t];
    __syncthreads();
    if (t < H) {
        float s = 0.f;
        #pragma unroll 8
        for (int k = 0; k < 64; k++) s += e[k] * w[k * H + t];
        out[t] = s;
    }
}

// ---------------- CSR build ----------------
__global__ void count_kernel(const int* __restrict__ edge, int e) {
    int i = blockIdx.x * blockDim.x + threadIdx.x;
    if (i < e) atomicAdd(&d_cnt[edge[e + i]], 1);
}

// single-pass scan with grid spin-sync (requires nb <= 128 blocks, all resident)
__global__ void scan_kernel(int n, int nb) {
    __shared__ int wsum[32];
    __shared__ int sb[128];
    __shared__ int btot;
    int t = threadIdx.x;
    int idx = blockIdx.x * 1024 + t;
    int v = (idx < n) ? d_cnt[idx] : 0;
    int lane = t & 31, wid = t >> 5;
    int inc = v;
    #pragma unroll
    for (int o = 1; o < 32; o <<= 1) {
        int u = __shfl_up_sync(0xffffffffu, inc, o);
        if (lane >= o) inc += u;
    }
    if (lane == 31) wsum[wid] = inc;
    __syncthreads();
    if (t < 32) {
        int s = wsum[t];
        int sInc = s;
        #pragma unroll
        for (int o = 1; o < 32; o <<= 1) {
            int u = __shfl_up_sync(0xffffffffu, sInc, o);
            if (t >= o) sInc += u;
        }
        wsum[t] = sInc - s;            // exclusive warp offsets
        if (t == 31) btot = sInc;      // block total
    }
    __syncthreads();
    // publish + grid sync
    if (t == 0) {
        d_bsum[blockIdx.x] = btot;
        __threadfence();
        atomicAdd(&d_done, 1);
        while (((volatile int*)&d_done)[0] < nb) { }
        __threadfence();
    }
    __syncthreads();
    // block-offset scan in smem
    if (t < 128) sb[t] = (t < nb) ? d_bsum[t] : 0;
    __syncthreads();
    #pragma unroll
    for (int o = 1; o < 128; o <<= 1) {
        int u = (t < 128 && t >= o) ? sb[t - o] : 0;
        __syncthreads();
        if (t < 128) sb[t] += u;
        __syncthreads();
    }
    int boff = (blockIdx.x == 0) ? 0 : sb[blockIdx.x - 1];
    if (blockIdx.x == 0 && t == 0) d_rowstart[n] = sb[nb - 1];
    if (idx < n) {
        int rs = boff + wsum[wid] + inc - v;
        d_rowstart[idx] = rs;
        d_cursor[idx] = rs;
    }
}

// fill: pack neighbor code into high bits (id < 2^17, code 11 bits)
__global__ void fill_kernel(const int* __restrict__ edge, int e) {
    int i = blockIdx.x * blockDim.x + threadIdx.x;
    if (i < e) {
        int s = edge[i];
        int d = edge[e + i];
        int p = atomicAdd(&d_cursor[d], 1);
        d_col[p] = (d_code[s] << 17) | s;
    }
}

// ---------------- fused GIN layer 0 as count-GEMM ----------------
__global__ void __launch_bounds__(256, 2)
gin0_kernel(const float* __restrict__ epsp, const float* __restrict__ b1,
            const float* __restrict__ w2, const float* __restrict__ b2,
            float* __restrict__ y,
            float* __restrict__ gsum, float* __restrict__ gsq, int n) {
    constexpr int KP1 = 92;    // 88 + 4 pad
    constexpr int KP2 = 132;   // 128 + 4 pad
    extern __shared__ float sm[];
    float* Cm = sm;                    // stage1 A: counts [128][92]
    float* Ts = sm + 13568;            // stage1 B: table [128 cols][92]
    float* hid = sm;                   // stage2 A: hidden [128][132]
    float* w2T = sm + 16896;           // stage2 B: [64][132]
    __shared__ float csum[64], csq[64];

    const int t = threadIdx.x;
    const int lane = t & 31, warp = t >> 5;
    const int g = lane >> 2, tig = lane & 3;
    const int rbase = warp * 16;
    const int node0 = blockIdx.x * 128;

    if (t < 64) { csum[t] = 0.f; csq[t] = 0.f; }
    for (int idx = t; idx < 128 * KP1; idx += 256) Cm[idx] = 0.f;
    for (int idx = t; idx < 128 * KP1; idx += 256) {
        int c = idx / KP1, k = idx - c * KP1;
        float v = 0.f;
        if (k < 65) v = d_Tdeg[k * 128 + c];
        else if (k < 81) v = d_Tlab[(k - 65) * 128 + c];
        Ts[idx] = to_tf32(v);
    }
    __syncthreads();

    // build counts: 2 threads per row, smem atomics
    {
        float e1 = 1.0f + epsp[0];
        int r = t >> 1, part = t & 1;
        int i = node0 + r;
        float* Crow = Cm + r * KP1;
        if (i < n) {
            if (part == 0) {
                int self = d_code[i];
                atomicAdd(&Crow[self >> 4], e1);
                atomicAdd(&Crow[65 + (self & 15)], e1);
            }
            int js = d_rowstart[i], je = d_rowstart[i + 1];
            for (int j = js + part; j < je; j += 2) {
                int cd = d_col[j] >> 17;
                atomicAdd(&Crow[cd >> 4], 1.0f);
                atomicAdd(&Crow[65 + (cd & 15)], 1.0f);
            }
        }
    }
    __syncthreads();

    // stage 1: agg(128 cols) = C @ T ; K=88
    float acc1[16][4];
    #pragma unroll
    for (int nt = 0; nt < 16; nt++)
        #pragma unroll
        for (int j = 0; j < 4; j++) acc1[nt][j] = 0.f;
    {
        const float* xr0 = Cm + (rbase + g) * KP1;
        const float* xr1 = Cm + (rbase + g + 8) * KP1;
        #pragma unroll
        for (int ks = 0; ks < 11; ks++) {
            int k0 = ks * 8;
            uint32_t a[4];
            a[0] = __float_as_uint(xr0[k0 + tig]);
            a[1] = __float_as_uint(xr1[k0 + tig]);
            a[2] = __float_as_uint(xr0[k0 + tig + 4]);
            a[3] = __float_as_uint(xr1[k0 + tig + 4]);
            #pragma unroll
            for (int nt = 0; nt < 16; nt++) {
                const float* wr = Ts + (nt * 8 + g) * KP1;
                uint32_t b[2];
                b[0] = __float_as_uint(wr[k0 + tig]);
                b[1] = __float_as_uint(wr[k0 + 4 + tig]);
                mma_tf32(acc1[nt], a, b);
            }
        }
    }
    __syncthreads();

    // hidden = tf32(lrelu(agg + b1)) -> hid; concurrently load w2T
    {
        float* h0 = hid + (rbase + g) * KP2;
        float* h1 = hid + (rbase + g + 8) * KP2;
        #pragma unroll
        for (int nt = 0; nt < 16; nt++) {
            int c = nt * 8 + 2 * tig;
            float2 bb = *(const float2*)(b1 + c);
            h0[c]     = to_tf32(lrelu(acc1[nt][0] + bb.x));
            h0[c + 1] = to_tf32(lrelu(acc1[nt][1] + bb.y));
            h1[c]     = to_tf32(lrelu(acc1[nt][2] + bb.x));
            h1[c + 1] = to_tf32(lrelu(acc1[nt][3] + bb.y));
        }
    }
    #pragma unroll
    for (int i = 0; i < 32; i++) {
        int idx = t + i * 256;
        int k = idx >> 6, nn = idx & 63;
        w2T[nn * KP2 + k] = to_tf32(w2[idx]);
    }
    __syncthreads();

    // stage 2: y = hidden @ w2 + b2
    float acc[8][4];
    #pragma unroll
    for (int nt = 0; nt < 8; nt++)
        #pragma unroll
        for (int j = 0; j < 4; j++) acc[nt][j] = 0.f;
    {
        const float* xr0 = hid + (rbase + g) * KP2;
        const float* xr1 = hid + (rbase + g + 8) * KP2;
        #pragma unroll
        for (int ks = 0; ks < 16; ks++) {
            int k0 = ks * 8;
            uint32_t a[4];
            a[0] = __float_as_uint(xr0[k0 + tig]);
            a[1] = __float_as_uint(xr1[k0 + tig]);
            a[2] = __float_as_uint(xr0[k0 + tig + 4]);
            a[3] = __float_as_uint(xr1[k0 + tig + 4]);
            #pragma unroll
            for (int nt = 0; nt < 8; nt++) {
                const float* wr = w2T + (nt * 8 + g) * KP2;
                uint32_t b[2];
                b[0] = __float_as_uint(wr[k0 + tig]);
                b[1] = __float_as_uint(wr[k0 + 4 + tig]);
                mma_tf32(acc[nt], a, b);
            }
        }
    }

    int r0 = node0 + rbase + g, r1 = r0 + 8;
    bool v0 = r0 < n, v1 = r1 < n;
    float ps[8][2], pq[8][2];
    #pragma unroll
    for (int nt = 0; nt < 8; nt++) {
        int c = nt * 8 + 2 * tig;
        float2 bb = *(const float2*)(b2 + c);
        float v00 = acc[nt][0] + bb.x, v01 = acc[nt][1] + bb.y;
        float v10 = acc[nt][2] + bb.x, v11 = acc[nt][3] + bb.y;
        float s0 = 0.f, s1 = 0.f, q0 = 0.f, q1 = 0.f;
        if (v0) { s0 += v00; s1 += v01; q0 += v00 * v00; q1 += v01 * v01; }
        if (v1) { s0 += v10; s1 += v11; q0 += v10 * v10; q1 += v11 * v11; }
        ps[nt][0] = s0; ps[nt][1] = s1; pq[nt][0] = q0; pq[nt][1] = q1;
        if (v0) *(float2*)(y + (size_t)r0 * 64 + c) = make_float2(v00, v01);
        if (v1) *(float2*)(y + (size_t)r1 * 64 + c) = make_float2(v10, v11);
    }
    #pragma unroll
    for (int o = 4; o <= 16; o <<= 1) {
        #pragma unroll
        for (int nt = 0; nt < 8; nt++) {
            ps[nt][0] += __shfl_xor_sync(0xffffffffu, ps[nt][0], o);
            ps[nt][1] += __shfl_xor_sync(0xffffffffu, ps[nt][1], o);
            pq[nt][0] += __shfl_xor_sync(0xffffffffu, pq[nt][0], o);
            pq[nt][1] += __shfl_xor_sync(0xffffffffu, pq[nt][1], o);
        }
    }
    if (lane < 4) {
        #pragma unroll
        for (int nt = 0; nt < 8; nt++) {
            int c = nt * 8 + 2 * tig;
            atomicAdd(&csum[c], ps[nt][0]);
            atomicAdd(&csum[c + 1], ps[nt][1]);
            atomicAdd(&csq[c], pq[nt][0]);
            atomicAdd(&csq[c + 1], pq[nt][1]);
        }
    }
    __syncthreads();
    if (t < 64) {
        atomicAdd(&gsum[t], csum[t]);
        atomicAdd(&gsq[t], csq[t]);
    }
}

// ---------------- layer-1 aggregation (fp16 source, fp32 accumulate, fp16 out) ----------------
__global__ void gather1_kernel(const float* __restrict__ epsp, int n) {
    int lane = threadIdx.x & 31;
    int warp = (blockIdx.x * blockDim.x + threadIdx.x) >> 5;
    int i = warp * 2 + (lane >> 4);
    int c = lane & 15;
    if (i >= n) return;
    float e1 = 1.0f + epsp[0];
    const uint2* hb2 = (const uint2*)d_XCh;
    uint2 raw = hb2[(size_t)i * 16 + c];
    float2 a01 = __half22float2(*(const __half2*)&raw.x);
    float2 a23 = __half22float2(*(const __half2*)&raw.y);
    float4 s = make_float4(a01.x * e1, a01.y * e1, a23.x * e1, a23.y * e1);
    int js = d_rowstart[i], je = d_rowstart[i + 1];
    for (int j = js; j < je; j++) {
        int nb = d_col[j] & 0x1FFFF;
        uint2 r = hb2[(size_t)nb * 16 + c];
        float2 v01 = __half22float2(*(const __half2*)&r.x);
        float2 v23 = __half22float2(*(const __half2*)&r.y);
        s.x += v01.x; s.y += v01.y; s.z += v23.x; s.w += v23.y;
    }
    uint2 pk;
    __half2 p0 = __floats2half2_rn(s.x, s.y);
    __half2 p1 = __floats2half2_rn(s.z, s.w);
    pk.x = *(const uint32_t*)&p0;
    pk.y = *(const uint32_t*)&p1;
    ((uint2*)d_aggh)[(size_t)i * 16 + c] = pk;
}

// ================= warp-level tf32 MMA GEMM building blocks =================
template <int K>
__device__ __forceinline__ void loadB_mma(float* wsT, const float* __restrict__ w, int t) {
    constexpr int KP = K + 4;
    #pragma unroll
    for (int i = 0; i < K * 64 / 256; i++) {
        int idx = t + i * 256;
        int k = idx >> 6, nn = idx & 63;
        wsT[nn * KP + k] = to_tf32(w[idx]);
    }
}

template <int K>
__device__ __forceinline__ void warp_mma(float (&acc)[8][4], const float* xs, const float* wsT,
                                         int rbase, int g, int tig) {
    constexpr int KP = K + 4;
    const float* xr0 = xs + (rbase + g) * KP;
    const float* xr1 = xs + (rbase + g + 8) * KP;
    #pragma unroll
    for (int ks = 0; ks < K / 8; ks++) {
        int k0 = ks * 8;
        uint32_t a[4];
        a[0] = __float_as_uint(xr0[k0 + tig]);
        a[1] = __float_as_uint(xr1[k0 + tig]);
        a[2] = __float_as_uint(xr0[k0 + tig + 4]);
        a[3] = __float_as_uint(xr1[k0 + tig + 4]);
        #pragma unroll
        for (int nt = 0; nt < 8; nt++) {
            const float* wr = wsT + (nt * 8 + g) * KP;
            uint32_t b[2];
            b[0] = __float_as_uint(wr[k0 + tig]);
            b[1] = __float_as_uint(wr[k0 + 4 + tig]);
            mma_tf32(acc[nt], a, b);
        }
    }
}

// stats + store epilogue
__device__ __forceinline__ void mma_store_stats(float (&acc)[8][4],
                                                const float2 (&bb0)[8], const float2 (&bb1)[8],
                                                int r0, int r1, bool v0, bool v1, int tig, int lane,
                                                float* __restrict__ y, float* csum, float* csq) {
    float ps[8][2], pq[8][2];
    #pragma unroll
    for (int nt = 0; nt < 8; nt++) {
        int c = nt * 8 + 2 * tig;
        float v00 = acc[nt][0] + bb0[nt].x, v01 = acc[nt][1] + bb0[nt].y;
        float v10 = acc[nt][2] + bb1[nt].x, v11 = acc[nt][3] + bb1[nt].y;
        float s0 = 0.f, s1 = 0.f, q0 = 0.f, q1 = 0.f;
        if (v0) { s0 += v00; s1 += v01; q0 += v00 * v00; q1 += v01 * v01; }
        if (v1) { s0 += v10; s1 += v11; q0 += v10 * v10; q1 += v11 * v11; }
        ps[nt][0] = s0; ps[nt][1] = s1; pq[nt][0] = q0; pq[nt][1] = q1;
        if (v0) *(float2*)(y + (size_t)r0 * 64 + c) = make_float2(v00, v01);
        if (v1) *(float2*)(y + (size_t)r1 * 64 + c) = make_float2(v10, v11);
    }
    #pragma unroll
    for (int o = 4; o <= 16; o <<= 1) {
        #pragma unroll
        for (int nt = 0; nt < 8; nt++) {
            ps[nt][0] += __shfl_xor_sync(0xffffffffu, ps[nt][0], o);
            ps[nt][1] += __shfl_xor_sync(0xffffffffu, ps[nt][1], o);
            pq[nt][0] += __shfl_xor_sync(0xffffffffu, pq[nt][0], o);
            pq[nt][1] += __shfl_xor_sync(0xffffffffu, pq[nt][1], o);
        }
    }
    if (lane < 4) {
        #pragma unroll
        for (int nt = 0; nt < 8; nt++) {
            int c = nt * 8 + 2 * tig;
            atomicAdd(&csum[c], ps[nt][0]);
            atomicAdd(&csum[c + 1], ps[nt][1]);
            atomicAdd(&csq[c], pq[nt][0]);
            atomicAdd(&csq[c + 1], pq[nt][1]);
        }
    }
}

// ---------------- layer-1 MLP (tf32 MMA, fp16 A source): y = lrelu(x@w1+b1)@w2+b2 ----------------
__global__ void __launch_bounds__(256, 2)
mmamlp1_kernel(const float* __restrict__ w1, const float* __restrict__ b1,
               const float* __restrict__ w2, const float* __restrict__ b2,
               float* __restrict__ y,
               float* __restrict__ gsum, float* __restrict__ gsq, int n) {
    constexpr int K = 64, KP = K + 4;
    extern __shared__ float sm[];
    float* xs   = sm;
    float* ws1T = sm + 128 * KP;
    float* ws2T = ws1T + 64 * KP;
    __shared__ float csum[64], csq[64];

    const int t = threadIdx.x;
    const int lane = t & 31, warp = t >> 5;
    const int g = lane >> 2, tig = lane & 3;
    const int rbase = warp * 16;
    const int node0 = blockIdx.x * 128;

    if (t < 64) { csum[t] = 0.f; csq[t] = 0.f; }
    {
        int r = t >> 1;
        int cb = (t & 1) * 32;
        int gn = node0 + r;
        const uint4* src = (const uint4*)(d_aggh + (size_t)gn * 64 + cb);
        float* dst = xs + r * KP + cb;
        #pragma unroll
        for (int i = 0; i < 4; i++) {
            uint4 v = (gn < n) ? src[i] : make_uint4(0u, 0u, 0u, 0u);
            float2 f0 = __half22float2(*(const __half2*)&v.x);
            float2 f1 = __half22float2(*(const __half2*)&v.y);
            float2 f2 = __half22float2(*(const __half2*)&v.z);
            float2 f3 = __half22float2(*(const __half2*)&v.w);
            dst[i * 8 + 0] = to_tf32(f0.x); dst[i * 8 + 1] = to_tf32(f0.y);
            dst[i * 8 + 2] = to_tf32(f1.x); dst[i * 8 + 3] = to_tf32(f1.y);
            dst[i * 8 + 4] = to_tf32(f2.x); dst[i * 8 + 5] = to_tf32(f2.y);
            dst[i * 8 + 6] = to_tf32(f3.x); dst[i * 8 + 7] = to_tf32(f3.y);
        }
    }
    loadB_mma<K>(ws1T, w1, t);
    loadB_mma<K>(ws2T, w2, t);
    __syncthreads();

    float acc[8][4];
    #pragma unroll
    for (int nt = 0; nt < 8; nt++)
        #pragma unroll
        for (int j = 0; j < 4; j++) acc[nt][j] = 0.f;

    warp_mma<K>(acc, xs, ws1T, rbase, g, tig);
    __syncwarp();
    {
        float* xr0 = xs + (rbase + g) * KP;
        float* xr1 = xs + (rbase + g + 8) * KP;
        #pragma unroll
        for (int nt = 0; nt < 8; nt++) {
            int c = nt * 8 + 2 * tig;
            float2 bb = *(const float2*)(b1 + c);
            xr0[c]     = to_tf32(lrelu(acc[nt][0] + bb.x));
            xr0[c + 1] = to_tf32(lrelu(acc[nt][1] + bb.y));
            xr1[c]     = to_tf32(lrelu(acc[nt][2] + bb.x));
            xr1[c + 1] = to_tf32(lrelu(acc[nt][3] + bb.y));
        }
    }
    __syncwarp();

    #pragma unroll
    for (int nt = 0; nt < 8; nt++)
        #pragma unroll
        for (int j = 0; j < 4; j++) acc[nt][j] = 0.f;

    warp_mma<K>(acc, xs, ws2T, rbase, g, tig);

    int r0 = node0 + rbase + g, r1 = r0 + 8;
    bool v0 = r0 < n, v1 = r1 < n;
    float2 bb0[8], bb1[8];
    #pragma unroll
    for (int nt = 0; nt < 8; nt++) {
        float2 b2v = *(const float2*)(b2 + nt * 8 + 2 * tig);
        bb0[nt] = b2v; bb1[nt] = b2v;
    }
    mma_store_stats(acc, bb0, bb1, r0, r1, v0, v1, tig, lane, y, csum, csq);

    __syncthreads();
    if (t < 64) {
        atomicAdd(&gsum[t], csum[t]);
        atomicAdd(&gsq[t], csq[t]);
    }
}

// ---------------- head GEMM: h1 from fp16 XCh; fused BN1-apply; code rowbias ----------------
__global__ void __launch_bounds__(256, 2)
headgemm_kernel(const float* __restrict__ ybuf_in,
                const float* __restrict__ w,
                const float* __restrict__ gsum1, const float* __restrict__ gsq1,
                const float* __restrict__ bn1g, const float* __restrict__ bn1b,
                const float* __restrict__ fc_b1,
                float* __restrict__ y,
                float* __restrict__ gsum, float* __restrict__ gsq, int n) {
    constexpr int K = 128, KP = K + 4;
    extern __shared__ float sm[];
    float* xs  = sm;
    float* wsT = sm + 128 * KP;
    __shared__ float csum[64], csq[64], sc[64], sh[64];

    const int t = threadIdx.x;
    const int lane = t & 31, warp = t >> 5;
    const int g = lane >> 2, tig = lane & 3;
    const int rbase = warp * 16;
    const int node0 = blockIdx.x * 128;

    if (t < 64) {
        csum[t] = 0.f; csq[t] = 0.f;
        float invn = 1.0f / (float)n;
        float m = gsum1[t] * invn;
        float var = gsq1[t] * invn - m * m;
        float s = bn1g[t] * rsqrtf(var + 1e-5f);
        sc[t] = s; sh[t] = bn1b[t] - m * s;
    }
    __syncthreads();

    loadB_mma<K>(wsT, w, t);
    // A tile: cols 0..63 = h1 (fp16 XCh), cols 64..127 = h2 = lrelu(bn1(ybuf))
    {
        int r = t >> 1;
        int gn = node0 + r;
        if ((t & 1) == 0) {
            const uint4* src = (const uint4*)(d_XCh + (size_t)gn * 64);
            float* dst = xs + r * KP;
            #pragma unroll
            for (int i = 0; i < 8; i++) {
                uint4 v = (gn < n) ? src[i] : make_uint4(0u, 0u, 0u, 0u);
                float2 f0 = __half22float2(*(const __half2*)&v.x);
                float2 f1 = __half22float2(*(const __half2*)&v.y);
                float2 f2 = __half22float2(*(const __half2*)&v.z);
                float2 f3 = __half22float2(*(const __half2*)&v.w);
                dst[i * 8 + 0] = to_tf32(f0.x); dst[i * 8 + 1] = to_tf32(f0.y);
                dst[i * 8 + 2] = to_tf32(f1.x); dst[i * 8 + 3] = to_tf32(f1.y);
                dst[i * 8 + 4] = to_tf32(f2.x); dst[i * 8 + 5] = to_tf32(f2.y);
                dst[i * 8 + 6] = to_tf32(f3.x); dst[i * 8 + 7] = to_tf32(f3.y);
            }
        } else {
            const float4* src = (const float4*)(ybuf_in + (size_t)gn * 64);
            float* dst = xs + r * KP + 64;
            #pragma unroll
            for (int i = 0; i < 16; i++) {
                float4 v = (gn < n) ? src[i] : make_float4(0.f, 0.f, 0.f, 0.f);
                int c = i * 4;
                dst[c + 0] = to_tf32(lrelu(v.x * sc[c + 0] + sh[c + 0]));
                dst[c + 1] = to_tf32(lrelu(v.y * sc[c + 1] + sh[c + 1]));
                dst[c + 2] = to_tf32(lrelu(v.z * sc[c + 2] + sh[c + 2]));
                dst[c + 3] = to_tf32(lrelu(v.w * sc[c + 3] + sh[c + 3]));
            }
        }
    }
    __syncthreads();

    float acc[8][4];
    #pragma unroll
    for (int nt = 0; nt < 8; nt++)
        #pragma unroll
        for (int j = 0; j < 4; j++) acc[nt][j] = 0.f;
    warp_mma<K>(acc, xs, wsT, rbase, g, tig);

    int r0 = node0 + rbase + g, r1 = r0 + 8;
    bool v0 = r0 < n, v1 = r1 < n;
    int code0 = v0 ? d_code[r0] : 0;
    int code1 = v1 ? d_code[r1] : 0;
    const float* fd0 = d_Fdeg + (code0 >> 4) * 64;
    const float* fl0 = d_Flab + (code0 & 15) * 64;
    const float* fd1 = d_Fdeg + (code1 >> 4) * 64;
    const float* fl1 = d_Flab + (code1 & 15) * 64;
    float2 bb0[8], bb1[8];
    #pragma unroll
    for (int nt = 0; nt < 8; nt++) {
        int c = nt * 8 + 2 * tig;
        float2 fb = *(const float2*)(fc_b1 + c);
        float2 a0 = *(const float2*)(fd0 + c);
        float2 l0 = *(const float2*)(fl0 + c);
        float2 a1 = *(const float2*)(fd1 + c);
        float2 l1 = *(const float2*)(fl1 + c);
        bb0[nt] = make_float2(a0.x + l0.x + fb.x, a0.y + l0.y + fb.y);
        bb1[nt] = make_float2(a1.x + l1.x + fb.x, a1.y + l1.y + fb.y);
    }
    mma_store_stats(acc, bb0, bb1, r0, r1, v0, v1, tig, lane, y, csum, csq);

    __syncthreads();
    if (t < 64) {
        atomicAdd(&gsum[t], csum[t]);
        atomicAdd(&gsq[t], csq[t]);
    }
}

// ---------------- BN apply + lrelu (layer 0): writes fp16 XCh only ----------------
__global__ void bnapply_kernel(const float* __restrict__ y,
                               const float* __restrict__ gsum, const float* __restrict__ gsq,
                               const float* __restrict__ g, const float* __restrict__ b, int n) {
    __shared__ float sc[64], sh[64];
    int t = threadIdx.x;
    if (t < 64) {
        float invn = 1.0f / (float)n;
        float m = gsum[t] * invn;
        float var = gsq[t] * invn - m * m;
        float s = g[t] * rsqrtf(var + 1e-5f);
        sc[t] = s; sh[t] = b[t] - m * s;
    }
    __syncthreads();
    int idx = blockIdx.x * blockDim.x + t;
    int i = idx >> 4, c = idx & 15;
    if (i >= n) return;
    float4 v = ((const float4*)y)[(size_t)i * 16 + c];
    v.x = lrelu(v.x * sc[c * 4 + 0] + sh[c * 4 + 0]);
    v.y = lrelu(v.y * sc[c * 4 + 1] + sh[c * 4 + 1]);
    v.z = lrelu(v.z * sc[c * 4 + 2] + sh[c * 4 + 2]);
    v.w = lrelu(v.w * sc[c * 4 + 3] + sh[c * 4 + 3]);
    uint2 pk;
    __half2 p0 = __floats2half2_rn(v.x, v.y);
    __half2 p1 = __floats2half2_rn(v.z, v.w);
    pk.x = *(const uint32_t*)&p0;
    pk.y = *(const uint32_t*)&p1;
    ((uint2*)d_XCh)[(size_t)i * 16 + c] = pk;
}

// ---------------- head: lrelu(bn(y)) @ fc_w2 + b2 -> sigmoid ----------------
__global__ void head_kernel(const float* __restrict__ y,
                            const float* __restrict__ gsum, const float* __restrict__ gsq,
                            const float* __restrict__ g, const float* __restrict__ b,
                            const float* __restrict__ w2, const float* __restrict__ b2,
                            float* __restrict__ out, int n) {
    __shared__ float sc[64], sh[64];
    int t = threadIdx.x;
    if (t < 64) {
        float invn = 1.0f / (float)n;
        float m = gsum[t] * invn;
        float var = gsq[t] * invn - m * m;
        float s = g[t] * rsqrtf(var + 1e-5f);
        sc[t] = s; sh[t] = b[t] - m * s;
    }
    __syncthreads();
    int lane = t & 31;
    int i = (blockIdx.x * blockDim.x + t) >> 5;
    if (i >= n) return;
    float2 v = ((const float2*)y)[(size_t)i * 32 + lane];
    float z0 = lrelu(v.x * sc[2 * lane] + sh[2 * lane]);
    float z1 = lrelu(v.y * sc[2 * lane + 1] + sh[2 * lane + 1]);
    float a = z0 * w2[2 * lane] + z1 * w2[2 * lane + 1];
    #pragma unroll
    for (int o = 16; o; o >>= 1) a += __shfl_xor_sync(0xffffffffu, a, o);
    if (lane == 0) out[i] = 1.0f / (1.0f + expf(-(a + b2[0])));
}

// ---------------- launch ----------------
extern "C" void kernel_launch(void* const* d_in, const int* in_sizes, int n_in,
                              void* d_out, int out_size) {
    const int*   node_deg = (const int*)d_in[0];
    const int*   node_lab = (const int*)d_in[1];
    const int*   edge     = (const int*)d_in[2];
    const float* emb_deg  = (const float*)d_in[3];
    const float* emb_lab  = (const float*)d_in[4];
    const float* l0_w1 = (const float*)d_in[5];
    const float* l0_b1 = (const float*)d_in[6];
    const float* l0_w2 = (const float*)d_in[7];
    const float* l0_b2 = (const float*)d_in[8];
    const float* l0_eps = (const float*)d_in[9];
    const float* bn0_g = (const float*)d_in[10];
    const float* bn0_b = (const float*)d_in[11];
    const float* l1_w1 = (const float*)d_in[12];
    const float* l1_b1 = (const float*)d_in[13];
    const float* l1_w2 = (const float*)d_in[14];
    const float* l1_b2 = (const float*)d_in[15];
    const float* l1_eps = (const float*)d_in[16];
    const float* bn1_g = (const float*)d_in[17];
    const float* bn1_b = (const float*)d_in[18];
    const float* fc_w1 = (const float*)d_in[19];
    const float* fc_b1 = (const float*)d_in[20];
    const float* fc_bn_g = (const float*)d_in[21];
    const float* fc_bn_b = (const float*)d_in[22];
    const float* fc_w2 = (const float*)d_in[23];
    const float* fc_b2 = (const float*)d_in[24];

    int n = in_sizes[0];
    int E = in_sizes[2] / 2;

    float *ybuf, *sumv, *sqv;
    cudaGetSymbolAddress((void**)&ybuf, d_ybuf);
    cudaGetSymbolAddress((void**)&sumv, d_sum);
    cudaGetSymbolAddress((void**)&sqv,  d_sq);

    const int SMEM_GIN0    = 25344 * 4;                        // 101376
    const int SMEM_GEMM128 = (128 + 64) * (128 + 4) * 4;       // 101376
    const int SMEM_MLP     = (128 + 64 + 64) * (64 + 4) * 4;   // 69632
    cudaFuncSetAttribute(gin0_kernel,     cudaFuncAttributeMaxDynamicSharedMemorySize, SMEM_GIN0);
    cudaFuncSetAttribute(headgemm_kernel, cudaFuncAttributeMaxDynamicSharedMemorySize, SMEM_GEMM128);
    cudaFuncSetAttribute(mmamlp1_kernel,  cudaFuncAttributeMaxDynamicSharedMemorySize, SMEM_MLP);

    int NB = (n + 1023) / 1024;
    int NZ = (n + 255) / 256;
    int NT = (n + 127) / 128;

    // init (+tables) + CSR build
    zero_tables_kernel<<<NZ + 162, 256>>>(node_deg, node_lab, emb_deg, emb_lab, l0_w1, fc_w1, n, NZ);
    count_kernel<<<(E + 255) / 256, 256>>>(edge, E);
    scan_kernel<<<NB, 1024>>>(n, NB);
    fill_kernel<<<(E + 255) / 256, 256>>>(edge, E);

    // ---- GIN layer 0: count-GEMM fused kernel ----
    gin0_kernel<<<NT, 256, SMEM_GIN0>>>(l0_eps, l0_b1, l0_w2, l0_b2, ybuf, sumv + 0, sqv + 0, n);
    bnapply_kernel<<<((size_t)n * 16 + 255) / 256, 256>>>(ybuf, sumv + 0, sqv + 0, bn0_g, bn0_b, n);

    // ---- GIN layer 1: fp16 gather -> fp16 agg -> MLP ----
    gather1_kernel<<<((size_t)((n + 1) / 2) * 32 + 255) / 256, 256>>>(l1_eps, n);
    mmamlp1_kernel<<<NT, 256, SMEM_MLP>>>(l1_w1, l1_b1, l1_w2, l1_b2, ybuf, sumv + 64, sqv + 64, n);

    // ---- head: fp16 h1 + fused BN1-apply + code rowbias ----
    headgemm_kernel<<<NT, 256, SMEM_GEMM128>>>(ybuf, fc_w1 + 128 * 64,
                                               sumv + 64, sqv + 64, bn1_g, bn1_b, fc_b1,
                                               ybuf, sumv + 128, sqv + 128, n);
    head_kernel<<<((size_t)n * 32 + 255) / 256, 256>>>(ybuf, sumv + 128, sqv + 128,
                                                       fc_bn_g, fc_bn_b, fc_w2, fc_b2, (float*)d_out, n);
}